// round 7
// baseline (speedup 1.0000x reference)
#include <cuda_runtime.h>
#include <cuda_bf16.h>
#include <math.h>
#include <stdint.h>

#define BB 4
#define SS 2048
#define DD 1024
#define FF 4096
#define HH 16
#define QKVD (3*DD)
#define INV_SCALE 0.125f
#define NEGBIG -1e30f
#define MROWS (BB*SS)

// weight plane offsets (int8 [N,K] packs)
#define OQKV 0
#define OWO  (QKVD*DD)
#define OW1  (OWO + DD*DD)
#define OW2  (OW1 + FF*DD)
#define W8TOT (OW2 + DD*FF)
#define SQKV 0
#define SWO  QKVD
#define SW1  (QKVD + DD)
#define SW2  (QKVD + DD + FF)
#define NSCALE (QKVD + DD + FF + DD)

// ---------------- scratch ------------------------------------------------------
__device__ int8_t g_x8a[MROWS*DD], g_x8b[MROWS*DD];
__device__ int8_t g_c8a[MROWS*DD], g_c8b[MROWS*DD];
__device__ int8_t g_y8a[MROWS*DD], g_y8b[MROWS*DD];
__device__ int8_t g_h8a[(size_t)MROWS*FF], g_h8b[(size_t)MROWS*FF];
__device__ float  g_sx[MROWS], g_sc[MROWS], g_sy[MROWS], g_sh[MROWS];
__device__ __nv_bfloat16 g_qh[(size_t)MROWS*QKVD], g_ql[(size_t)MROWS*QKVD];
__device__ float  g_ctx[MROWS*DD], g_x2[MROWS*DD], g_hf[(size_t)MROWS*FF];
__device__ int8_t g_w8a[W8TOT], g_w8b[W8TOT];
__device__ unsigned g_swb[NSCALE];
__device__ float  g_swf[NSCALE];

// ---------------- helpers ------------------------------------------------------
__device__ __forceinline__ uint32_t split_pack(float a, float b, uint32_t& lo) {
    __nv_bfloat16 ha = __float2bfloat16(a), hb = __float2bfloat16(b);
    __nv_bfloat16 la = __float2bfloat16(a - __bfloat162float(ha));
    __nv_bfloat16 lb = __float2bfloat16(b - __bfloat162float(hb));
    lo = (uint32_t)__bfloat16_as_ushort(la) | ((uint32_t)__bfloat16_as_ushort(lb) << 16);
    return (uint32_t)__bfloat16_as_ushort(ha) | ((uint32_t)__bfloat16_as_ushort(hb) << 16);
}
__device__ __forceinline__ void hmma(float* d, uint32_t a0, uint32_t a1,
                                     uint32_t a2, uint32_t a3,
                                     uint32_t b0, uint32_t b1) {
    asm volatile("mma.sync.aligned.m16n8k16.row.col.f32.bf16.bf16.f32 "
                 "{%0,%1,%2,%3}, {%4,%5,%6,%7}, {%8,%9}, {%0,%1,%2,%3};"
                 : "+f"(d[0]), "+f"(d[1]), "+f"(d[2]), "+f"(d[3])
                 : "r"(a0), "r"(a1), "r"(a2), "r"(a3), "r"(b0), "r"(b1));
}
__device__ __forceinline__ void imma(int* d, uint32_t a0, uint32_t a1,
                                     uint32_t a2, uint32_t a3,
                                     uint32_t b0, uint32_t b1) {
    asm volatile("mma.sync.aligned.m16n8k32.row.col.s32.s8.s8.s32 "
                 "{%0,%1,%2,%3}, {%4,%5,%6,%7}, {%8,%9}, {%0,%1,%2,%3};"
                 : "+r"(d[0]), "+r"(d[1]), "+r"(d[2]), "+r"(d[3])
                 : "r"(a0), "r"(a1), "r"(a2), "r"(a3), "r"(b0), "r"(b1));
}
__device__ __forceinline__ uint32_t s2u(const void* p) {
    return (uint32_t)__cvta_generic_to_shared(p);
}
__device__ __forceinline__ void cp16(uint32_t dst, const void* src) {
    asm volatile("cp.async.ca.shared.global [%0], [%1], 16;" :: "r"(dst), "l"(src));
}
__device__ __forceinline__ void cp_commit() { asm volatile("cp.async.commit_group;"); }
__device__ __forceinline__ void cp_wait0()  { asm volatile("cp.async.wait_group 0;"); }
__device__ __forceinline__ void cp_wait1()  { asm volatile("cp.async.wait_group 1;"); }
__device__ __forceinline__ void ldm4(uint32_t addr, uint32_t& r0, uint32_t& r1,
                                     uint32_t& r2, uint32_t& r3) {
    asm volatile("ldmatrix.sync.aligned.m8n8.x4.shared.b16 {%0,%1,%2,%3}, [%4];"
                 : "=r"(r0), "=r"(r1), "=r"(r2), "=r"(r3) : "r"(addr));
}
__device__ __forceinline__ void ldm4t(uint32_t addr, uint32_t& r0, uint32_t& r1,
                                      uint32_t& r2, uint32_t& r3) {
    asm volatile("ldmatrix.sync.aligned.m8n8.x4.trans.shared.b16 {%0,%1,%2,%3}, [%4];"
                 : "=r"(r0), "=r"(r1), "=r"(r2), "=r"(r3) : "r"(addr));
}

// ---------------- weight quantization ------------------------------------------
__global__ void zero_scales(unsigned* bits, int n) {
    int i = blockIdx.x * 256 + threadIdx.x;
    if (i < n) bits[i] = 0;
}
// W [K,N] fp32 -> per-col absmax into bits (float bits, atomicMax on non-neg)
__global__ __launch_bounds__(256)
void colmax_w(const float* __restrict__ W, unsigned* bits, int K, int N)
{
    int n = blockIdx.x * 256 + threadIdx.x;
    int ks = K >> 3;
    int k0 = blockIdx.y * ks;
    float m = 0.f;
    for (int k = k0; k < k0 + ks; k++)
        m = fmaxf(m, fabsf(W[(size_t)k * N + n]));
    atomicMax(bits + n, __float_as_uint(m));
}
__global__ void finalize_scales(const unsigned* bits, float* s, int n) {
    int i = blockIdx.x * 256 + threadIdx.x;
    if (i < n) s[i] = fmaxf(__uint_as_float(bits[i]), 1e-30f) * (1.f / 127.f);
}
// W [K,N] -> q1,q2 int8 [N,K] using s[n]
__global__ __launch_bounds__(256)
void quantsplit_w(const float* __restrict__ W, int8_t* __restrict__ q1,
                  int8_t* __restrict__ q2, const float* __restrict__ s,
                  int K, int N)
{
    __shared__ float tile[32][33];
    int n0 = blockIdx.x * 32, k0 = blockIdx.y * 32;
    int tx = threadIdx.x & 31, ty = threadIdx.x >> 5;
    for (int j = ty; j < 32; j += 8)
        tile[j][tx] = W[(size_t)(k0 + j) * N + n0 + tx];
    __syncthreads();
    for (int j = ty; j < 32; j += 8) {
        float val = tile[tx][j];          // W[k0+tx][n0+j]
        float q = val / s[n0 + j];
        int a1 = __float2int_rn(q);
        int a2 = __float2int_rn((q - (float)a1) * 252.f);
        size_t o = (size_t)(n0 + j) * K + k0 + tx;
        q1[o] = (int8_t)a1;
        q2[o] = (int8_t)a2;
    }
}

// ---------------- fused LayerNorm + rowwise int8 quant --------------------------
__global__ __launch_bounds__(256)
void ln_quant(const float* __restrict__ x, const float* __restrict__ g,
              const float* __restrict__ b, int8_t* __restrict__ q1,
              int8_t* __restrict__ q2, float* __restrict__ sA)
{
    int row = blockIdx.x, tid = threadIdx.x;
    const float* xr = x + (size_t)row * DD;
    float4 v = reinterpret_cast<const float4*>(xr)[tid];
    float s  = v.x + v.y + v.z + v.w;
    float sq = v.x*v.x + v.y*v.y + v.z*v.z + v.w*v.w;
    #pragma unroll
    for (int o = 16; o > 0; o >>= 1) {
        s  += __shfl_xor_sync(0xffffffffu, s,  o);
        sq += __shfl_xor_sync(0xffffffffu, sq, o);
    }
    __shared__ float ws[8], wq[8], wm[8];
    __shared__ float smean, srstd, sscale;
    int wid = tid >> 5, lane = tid & 31;
    if (lane == 0) { ws[wid] = s; wq[wid] = sq; }
    __syncthreads();
    if (tid == 0) {
        float S = 0.f, Q = 0.f;
        #pragma unroll
        for (int i = 0; i < 8; i++) { S += ws[i]; Q += wq[i]; }
        float mean = S * (1.f / DD);
        float var  = fmaxf(Q * (1.f / DD) - mean * mean, 0.f);
        smean = mean;
        srstd = rsqrtf(var + 1e-12f);
    }
    __syncthreads();
    float mean = smean, rstd = srstd;
    float4 gv = reinterpret_cast<const float4*>(g)[tid];
    float4 bv = reinterpret_cast<const float4*>(b)[tid];
    float o0 = (v.x - mean) * rstd * gv.x + bv.x;
    float o1 = (v.y - mean) * rstd * gv.y + bv.y;
    float o2 = (v.z - mean) * rstd * gv.z + bv.z;
    float o3 = (v.w - mean) * rstd * gv.w + bv.w;
    float mx = fmaxf(fmaxf(fabsf(o0), fabsf(o1)), fmaxf(fabsf(o2), fabsf(o3)));
    #pragma unroll
    for (int o = 16; o > 0; o >>= 1)
        mx = fmaxf(mx, __shfl_xor_sync(0xffffffffu, mx, o));
    if (lane == 0) wm[wid] = mx;
    __syncthreads();
    if (tid == 0) {
        float M = 0.f;
        #pragma unroll
        for (int i = 0; i < 8; i++) M = fmaxf(M, wm[i]);
        sscale = fmaxf(M, 1e-20f) * (1.f / 127.f);
    }
    __syncthreads();
    float sc = sscale, inv = 1.f / sc;
    float qf[4] = {o0 * inv, o1 * inv, o2 * inv, o3 * inv};
    char a1[4], a2[4];
    #pragma unroll
    for (int i = 0; i < 4; i++) {
        int i1 = __float2int_rn(qf[i]);
        int i2 = __float2int_rn((qf[i] - (float)i1) * 252.f);
        a1[i] = (char)i1; a2[i] = (char)i2;
    }
    reinterpret_cast<char4*>(q1 + (size_t)row * DD)[tid] = make_char4(a1[0], a1[1], a1[2], a1[3]);
    reinterpret_cast<char4*>(q2 + (size_t)row * DD)[tid] = make_char4(a2[0], a2[1], a2[2], a2[3]);
    if (tid == 0) sA[row] = sc;
}

// ---------------- plain rowwise quant (ctx, h) ----------------------------------
__global__ __launch_bounds__(256)
void quant_rows(const float* __restrict__ x, int8_t* __restrict__ q1,
                int8_t* __restrict__ q2, float* __restrict__ sA, int N)
{
    int row = blockIdx.x, tid = threadIdx.x;
    const float* xr = x + (size_t)row * N;
    int vpt = N >> 10;          // float4s per thread (1 or 4)
    float4 v[4];
    float mx = 0.f;
    for (int j = 0; j < vpt; j++) {
        v[j] = reinterpret_cast<const float4*>(xr)[j * 256 + tid];
        mx = fmaxf(mx, fmaxf(fmaxf(fabsf(v[j].x), fabsf(v[j].y)),
                             fmaxf(fabsf(v[j].z), fabsf(v[j].w))));
    }
    #pragma unroll
    for (int o = 16; o > 0; o >>= 1)
        mx = fmaxf(mx, __shfl_xor_sync(0xffffffffu, mx, o));
    __shared__ float wm[8];
    __shared__ float sscale;
    int wid = tid >> 5, lane = tid & 31;
    if (lane == 0) wm[wid] = mx;
    __syncthreads();
    if (tid == 0) {
        float M = 0.f;
        #pragma unroll
        for (int i = 0; i < 8; i++) M = fmaxf(M, wm[i]);
        sscale = fmaxf(M, 1e-20f) * (1.f / 127.f);
    }
    __syncthreads();
    float inv = 1.f / sscale;
    for (int j = 0; j < vpt; j++) {
        float qf[4] = {v[j].x * inv, v[j].y * inv, v[j].z * inv, v[j].w * inv};
        char a1[4], a2[4];
        #pragma unroll
        for (int i = 0; i < 4; i++) {
            int i1 = __float2int_rn(qf[i]);
            int i2 = __float2int_rn((qf[i] - (float)i1) * 252.f);
            a1[i] = (char)i1; a2[i] = (char)i2;
        }
        reinterpret_cast<char4*>(q1 + (size_t)row * N)[j * 256 + tid] =
            make_char4(a1[0], a1[1], a1[2], a1[3]);
        reinterpret_cast<char4*>(q2 + (size_t)row * N)[j * 256 + tid] =
            make_char4(a2[0], a2[1], a2[2], a2[3]);
    }
    if (tid == 0) sA[row] = sscale;
}

// ---------------- int8x3 IMMA GEMM: 128x128 tile, 512 thr, BK=64, 2-stage -------
#define I8_ASTR 40                     // b16 units per row (64 int8 = 32 b16 + pad)
#define I8_PL (128*I8_ASTR)            // plane size in b16
#define I8_STG (4*I8_PL)               // A1,A2,B1,B2
#define I8_SMEM (2*I8_STG*2)           // bytes (81920)

__global__ __launch_bounds__(512, 1)
void gemm_i8(const int8_t* __restrict__ A1, const int8_t* __restrict__ A2,
             const float* __restrict__ sA,
             const int8_t* __restrict__ B1, const int8_t* __restrict__ B2,
             const float* __restrict__ sB,
             const float* __restrict__ bias, const float* __restrict__ res,
             float* __restrict__ outF,
             __nv_bfloat16* __restrict__ outH, __nv_bfloat16* __restrict__ outL,
             int M, int N, int K, int act)
{
    extern __shared__ uint16_t sh[];
    uint32_t sb = s2u(sh);
    int tid = threadIdx.x;
    int wid = tid >> 5, lane = tid & 31;
    int g = lane >> 2, tg = lane & 3;
    int q8 = lane >> 3, e8 = lane & 7;
    int warp_m = wid & 3, warp_n = wid >> 2;     // 4x4, warp tile 32x32
    int m0 = blockIdx.y * 128, n0 = blockIdx.x * 128;

    int accM[2][4][4], accC[2][4][4];
    #pragma unroll
    for (int mt = 0; mt < 2; mt++)
        #pragma unroll
        for (int nt = 0; nt < 4; nt++)
            #pragma unroll
            for (int c = 0; c < 4; c++) { accM[mt][nt][c] = 0; accC[mt][nt][c] = 0; }

    // cp.async: 2048 x 16B per stage -> 4/thread
    const int8_t* gp[4];
    uint32_t so[4];
    #pragma unroll
    for (int u = 0; u < 4; u++) {
        int f = tid + u * 512;
        int half = f >> 10;            // 0=A, 1=B
        int plane = (f >> 9) & 1;
        int fr = f & 511;
        int row = fr >> 2, ch = fr & 3;
        const int8_t* base = half ? (plane ? B2 : B1) : (plane ? A2 : A1);
        int grow = (half ? n0 : m0) + row;
        gp[u] = base + (size_t)grow * K + ch * 16;
        so[u] = (uint32_t)((half * 2 + plane) * I8_PL + row * I8_ASTR + ch * 8) * 2;
    }
    const int T = K >> 6;

    auto issue = [&](int t) {
        uint32_t st = sb + (uint32_t)(t & 1) * (I8_STG * 2);
        int k0 = t << 6;
        #pragma unroll
        for (int u = 0; u < 4; u++) cp16(st + so[u], gp[u] + k0);
        cp_commit();
    };

    issue(0);

    uint32_t aoff[2], boff[2];
    #pragma unroll
    for (int mt = 0; mt < 2; mt++)
        aoff[mt] = (uint32_t)((warp_m * 32 + mt * 16 + e8 + (q8 & 1) * 8) * I8_ASTR
                              + (q8 >> 1) * 8);
    #pragma unroll
    for (int p = 0; p < 2; p++)
        boff[p] = (uint32_t)((warp_n * 32 + (2 * p + (q8 >> 1)) * 8 + e8) * I8_ASTR
                             + (q8 & 1) * 8);

    for (int t = 0; t < T; t++) {
        cp_wait0();
        __syncthreads();
        if (t + 1 < T) issue(t + 1);

        uint32_t st = sb + (uint32_t)(t & 1) * (I8_STG * 2);
        #pragma unroll
        for (int s = 0; s < 32; s += 16) {     // two k32 slices (b16 offset)
            uint32_t a1f[2][4], a2f[2][4];
            #pragma unroll
            for (int mt = 0; mt < 2; mt++) {
                ldm4(st + (aoff[mt] + s) * 2,
                     a1f[mt][0], a1f[mt][1], a1f[mt][2], a1f[mt][3]);
                ldm4(st + (I8_PL + aoff[mt] + s) * 2,
                     a2f[mt][0], a2f[mt][1], a2f[mt][2], a2f[mt][3]);
            }
            #pragma unroll
            for (int p = 0; p < 2; p++) {
                uint32_t b10, b11, b12, b13, b20, b21, b22, b23;
                ldm4(st + (2 * I8_PL + boff[p] + s) * 2, b10, b11, b12, b13);
                ldm4(st + (3 * I8_PL + boff[p] + s) * 2, b20, b21, b22, b23);
                int ntA = 2 * p, ntB = ntA + 1;
                #pragma unroll
                for (int mt = 0; mt < 2; mt++) {
                    imma(accM[mt][ntA], a1f[mt][0], a1f[mt][1], a1f[mt][2], a1f[mt][3], b10, b11);
                    imma(accC[mt][ntA], a1f[mt][0], a1f[mt][1], a1f[mt][2], a1f[mt][3], b20, b21);
                    imma(accC[mt][ntA], a2f[mt][0], a2f[mt][1], a2f[mt][2], a2f[mt][3], b10, b11);
                    imma(accM[mt][ntB], a1f[mt][0], a1f[mt][1], a1f[mt][2], a1f[mt][3], b12, b13);
                    imma(accC[mt][ntB], a1f[mt][0], a1f[mt][1], a1f[mt][2], a1f[mt][3], b22, b23);
                    imma(accC[mt][ntB], a2f[mt][0], a2f[mt][1], a2f[mt][2], a2f[mt][3], b12, b13);
                }
            }
        }
    }

    // ---- epilogue ----
    #pragma unroll
    for (int mt = 0; mt < 2; mt++) {
        #pragma unroll
        for (int nt = 0; nt < 4; nt++) {
            int row = m0 + warp_m * 32 + mt * 16 + g;
            int col = n0 + warp_n * 32 + nt * 8 + 2 * tg;
            float sb0 = __ldg(sB + col), sb1 = __ldg(sB + col + 1);
            #pragma unroll
            for (int half = 0; half < 2; half++) {
                int r = row + half * 8;
                float sa = __ldg(sA + r);
                float v0 = sa * sb0 * ((float)accM[mt][nt][half * 2 + 0]
                            + (float)accC[mt][nt][half * 2 + 0] * (1.f / 252.f));
                float v1 = sa * sb1 * ((float)accM[mt][nt][half * 2 + 1]
                            + (float)accC[mt][nt][half * 2 + 1] * (1.f / 252.f));
                if (bias) { v0 += bias[col]; v1 += bias[col + 1]; }
                if (act) {
                    v0 = v0 / (1.f + __expf(-v0));
                    v1 = v1 / (1.f + __expf(-v1));
                }
                size_t o = (size_t)r * N + col;
                if (outF) {
                    if (res) {
                        float2 rv = *reinterpret_cast<const float2*>(res + o);
                        v0 += rv.x; v1 += rv.y;
                    }
                    *reinterpret_cast<float2*>(outF + o) = make_float2(v0, v1);
                } else {
                    uint32_t lo;
                    uint32_t hi = split_pack(v0, v1, lo);
                    *reinterpret_cast<uint32_t*>(outH + o) = hi;
                    *reinterpret_cast<uint32_t*>(outL + o) = lo;
                }
            }
        }
    }
}

// ---------------- tensor-core flash attention (bf16x3, unchanged core) ----------
#define AT_STRIDE 72
#define QPB (128*AT_STRIDE*2)
#define KPB (64*AT_STRIDE*2)
#define KV_BASE (2*QPB)
#define AT_SMEM_BYTES (KV_BASE + 8*KPB + 3*64*4)

__global__ __launch_bounds__(256)
void attn_tc(const __nv_bfloat16* __restrict__ qh, const __nv_bfloat16* __restrict__ ql,
             const int* __restrict__ amask, float* __restrict__ ctx)
{
    extern __shared__ uint16_t ash[];
    uint32_t sb = s2u(ash);
    float* koff = reinterpret_cast<float*>((char*)ash + KV_BASE + 8 * KPB);

    int tid = threadIdx.x;
    int lane = tid & 31, w = tid >> 5;
    int g = lane >> 2, tg = lane & 3;
    int q8 = lane >> 3, e8 = lane & 7;
    int bh = blockIdx.y;
    int b = bh >> 4, h = bh & 15;
    int qt = gridDim.x - 1 - blockIdx.x;
    int q0 = qt * 128;
    const size_t rowbase = (size_t)b * SS;
    const int hoff = h * 64;
    const int ktmax = 2 * qt + 1;

    const __nv_bfloat16* qgp[8]; uint32_t qso[8];
    #pragma unroll
    for (int u = 0; u < 8; u++) {
        int f = tid + u * 256;
        int plane = f >> 10, fr = f & 1023;
        int row = fr >> 3, c = (fr & 7) << 3;
        qgp[u] = (plane ? ql : qh) + (rowbase + q0 + row) * QKVD + hoff + c;
        qso[u] = (uint32_t)(plane * (QPB / 2) + row * AT_STRIDE + c) * 2;
    }
    const __nv_bfloat16* kvgp[8]; uint32_t kvso[8]; int kvrow[8];
    #pragma unroll
    for (int u = 0; u < 8; u++) {
        int f = tid + u * 256;
        int plane = f >> 9, fr = f & 511;
        int row = fr >> 3, c = (fr & 7) << 3;
        const __nv_bfloat16* base = (plane == 0) ? qh + DD : (plane == 1) ? ql + DD
                                   : (plane == 2) ? qh + 2 * DD : ql + 2 * DD;
        kvgp[u] = base + rowbase * QKVD + hoff + c;
        kvrow[u] = row;
        kvso[u] = (uint32_t)KV_BASE + (uint32_t)(plane * (KPB / 2) + row * AT_STRIDE + c) * 2;
    }

    auto issueKV = [&](int kt) {
        uint32_t st = sb + (uint32_t)(kt & 1) * (4 * KPB);
        int k0 = kt * 64;
        #pragma unroll
        for (int u = 0; u < 8; u++)
            cp16(st + kvso[u], kvgp[u] + (size_t)(k0 + kvrow[u]) * QKVD);
        cp_commit();
        if (tid < 64)
            koff[(kt % 3) * 64 + tid] = (amask[b * SS + k0 + tid] == 1) ? 0.f : NEGBIG;
    };

    #pragma unroll
    for (int u = 0; u < 8; u++) cp16(sb + qso[u], qgp[u]);
    cp_commit();
    issueKV(0);
    issueKV(1);
    cp_wait1();
    __syncthreads();

    uint32_t qfh[4][4], qfl[4][4];
    uint32_t qoffb = (uint32_t)((w * 16 + e8 + (q8 & 1) * 8) * AT_STRIDE + (q8 >> 1) * 8);
    #pragma unroll
    for (int kt = 0; kt < 4; kt++) {
        ldm4(sb + (qoffb + 16 * kt) * 2, qfh[kt][0], qfh[kt][1], qfh[kt][2], qfh[kt][3]);
        ldm4(sb + QPB + (qoffb + 16 * kt) * 2,
             qfl[kt][0], qfl[kt][1], qfl[kt][2], qfl[kt][3]);
    }

    uint32_t kboff[4], vboff[4];
    #pragma unroll
    for (int p = 0; p < 4; p++) {
        kboff[p] = (uint32_t)(((2 * p + (q8 >> 1)) * 8 + e8) * AT_STRIDE + (q8 & 1) * 8);
        vboff[p] = (uint32_t)(((q8 & 1) * 8 + e8) * AT_STRIDE + (2 * p + (q8 >> 1)) * 8);
    }

    float o[8][4];
    #pragma unroll
    for (int nt = 0; nt < 8; nt++)
        #pragma unroll
        for (int c = 0; c < 4; c++) o[nt][c] = 0.f;
    float m0v = NEGBIG, m1v = NEGBIG, l0 = 0.f, l1 = 0.f;
    int r0g = q0 + w * 16 + g, r1g = r0g + 8;

    for (int kt_g = 0; kt_g <= ktmax; kt_g++) {
        int k0 = kt_g * 64;
        if (kt_g == ktmax) cp_wait0(); else cp_wait1();
        __syncthreads();

        uint32_t st = sb + (uint32_t)(kt_g & 1) * (4 * KPB);
        uint32_t stK  = st + KV_BASE;
        uint32_t stKl = stK + KPB;
        uint32_t stV  = stK + 2 * KPB;
        uint32_t stVl = stK + 3 * KPB;
        const float* kofft = koff + (kt_g % 3) * 64;

        float s[8][4];
        #pragma unroll
        for (int nt = 0; nt < 8; nt++)
            #pragma unroll
            for (int c = 0; c < 4; c++) s[nt][c] = 0.f;
        #pragma unroll
        for (int kt = 0; kt < 4; kt++) {
            #pragma unroll
            for (int p = 0; p < 4; p++) {
                uint32_t bh0, bh1, bh2, bh3, bl0, bl1, bl2, bl3;
                ldm4(stK  + (kboff[p] + 16 * kt) * 2, bh0, bh1, bh2, bh3);
                ldm4(stKl + (kboff[p] + 16 * kt) * 2, bl0, bl1, bl2, bl3);
                int ntA = 2 * p, ntB = ntA + 1;
                hmma(s[ntA], qfh[kt][0], qfh[kt][1], qfh[kt][2], qfh[kt][3], bh0, bh1);
                hmma(s[ntA], qfh[kt][0], qfh[kt][1], qfh[kt][2], qfh[kt][3], bl0, bl1);
                hmma(s[ntA], qfl[kt][0], qfl[kt][1], qfl[kt][2], qfl[kt][3], bh0, bh1);
                hmma(s[ntB], qfh[kt][0], qfh[kt][1], qfh[kt][2], qfh[kt][3], bh2, bh3);
                hmma(s[ntB], qfh[kt][0], qfh[kt][1], qfh[kt][2], qfh[kt][3], bl2, bl3);
                hmma(s[ntB], qfl[kt][0], qfl[kt][1], qfl[kt][2], qfl[kt][3], bh2, bh3);
            }
        }

        float mx0 = NEGBIG, mx1 = NEGBIG;
        #pragma unroll
        for (int nt = 0; nt < 8; nt++) {
            int c0 = k0 + 8 * nt + 2 * tg;
            float kf0 = kofft[8 * nt + 2 * tg], kf1 = kofft[8 * nt + 2 * tg + 1];
            float v0 = s[nt][0] * INV_SCALE + kf0;
            float v1 = s[nt][1] * INV_SCALE + kf1;
            float v2 = s[nt][2] * INV_SCALE + kf0;
            float v3 = s[nt][3] * INV_SCALE + kf1;
            if (c0     > r0g) v0 = NEGBIG;
            if (c0 + 1 > r0g) v1 = NEGBIG;
            if (c0     > r1g) v2 = NEGBIG;
            if (c0 + 1 > r1g) v3 = NEGBIG;
            s[nt][0] = v0; s[nt][1] = v1; s[nt][2] = v2; s[nt][3] = v3;
            mx0 = fmaxf(mx0, fmaxf(v0, v1));
            mx1 = fmaxf(mx1, fmaxf(v2, v3));
        }
        mx0 = fmaxf(mx0, __shfl_xor_sync(0xffffffffu, mx0, 1));
        mx0 = fmaxf(mx0, __shfl_xor_sync(0xffffffffu, mx0, 2));
        mx1 = fmaxf(mx1, __shfl_xor_sync(0xffffffffu, mx1, 1));
        mx1 = fmaxf(mx1, __shfl_xor_sync(0xffffffffu, mx1, 2));

        float mn0 = fmaxf(m0v, mx0), mn1 = fmaxf(m1v, mx1);
        float al0 = __expf(m0v - mn0), al1 = __expf(m1v - mn1);
        m0v = mn0; m1v = mn1;
        l0 *= al0; l1 *= al1;

        #pragma unroll
        for (int nt = 0; nt < 8; nt++) {
            float p0 = __expf(s[nt][0] - m0v);
            float p1 = __expf(s[nt][1] - m0v);
            float p2 = __expf(s[nt][2] - m1v);
            float p3 = __expf(s[nt][3] - m1v);
            s[nt][0] = p0; s[nt][1] = p1; s[nt][2] = p2; s[nt][3] = p3;
            l0 += p0 + p1; l1 += p2 + p3;
        }
        #pragma unroll
        for (int nt = 0; nt < 8; nt++) {
            o[nt][0] *= al0; o[nt][1] *= al0;
            o[nt][2] *= al1; o[nt][3] *= al1;
        }

        #pragma unroll
        for (int ktP = 0; ktP < 4; ktP++) {
            int ntA = 2 * ktP, ntB = ntA + 1;
            uint32_t a0l, a1l, a2l, a3l;
            uint32_t a0h = split_pack(s[ntA][0], s[ntA][1], a0l);
            uint32_t a1h = split_pack(s[ntA][2], s[ntA][3], a1l);
            uint32_t a2h = split_pack(s[ntB][0], s[ntB][1], a2l);
            uint32_t a3h = split_pack(s[ntB][2], s[ntB][3], a3l);
            #pragma unroll
            for (int p = 0; p < 4; p++) {
                uint32_t bh0, bh1, bh2, bh3, bl0, bl1, bl2, bl3;
                ldm4t(stV  + (vboff[p] + 16 * ktP * AT_STRIDE) * 2, bh0, bh1, bh2, bh3);
                ldm4t(stVl + (vboff[p] + 16 * ktP * AT_STRIDE) * 2, bl0, bl1, bl2, bl3);
                int n2A = 2 * p, n2B = n2A + 1;
                hmma(o[n2A], a0h, a1h, a2h, a3h, bh0, bh1);
                hmma(o[n2A], a0l, a1l, a2l, a3l, bh0, bh1);
                hmma(o[n2A], a0h, a1h, a2h, a3h, bl0, bl1);
                hmma(o[n2B], a0h, a1h, a2h, a3h, bh2, bh3);
                hmma(o[n2B], a0l, a1l, a2l, a3l, bh2, bh3);
                hmma(o[n2B], a0h, a1h, a2h, a3h, bl2, bl3);
            }
        }

        __syncthreads();
        if (kt_g + 2 <= ktmax) issueKV(kt_g + 2);
    }

    l0 += __shfl_xor_sync(0xffffffffu, l0, 1);
    l0 += __shfl_xor_sync(0xffffffffu, l0, 2);
    l1 += __shfl_xor_sync(0xffffffffu, l1, 1);
    l1 += __shfl_xor_sync(0xffffffffu, l1, 2);
    float inv0 = 1.f / l0, inv1 = 1.f / l1;

    #pragma unroll
    for (int nt = 0; nt < 8; nt++) {
        int col = hoff + 8 * nt + 2 * tg;
        *reinterpret_cast<float2*>(ctx + (rowbase + r0g) * DD + col) =
            make_float2(o[nt][0] * inv0, o[nt][1] * inv0);
        *reinterpret_cast<float2*>(ctx + (rowbase + r1g) * DD + col) =
            make_float2(o[nt][2] * inv1, o[nt][3] * inv1);
    }
}

// ---------------- host ---------------------------------------------------------
extern "C" void kernel_launch(void* const* d_in, const int* in_sizes, int n_in,
                              void* d_out, int out_size)
{
    const float* hidden = (const float*)d_in[0];
    const int*   amask  = (const int*)  d_in[1];
    const float* Wq     = (const float*)d_in[2];
    const float* Wk     = (const float*)d_in[3];
    const float* Wv     = (const float*)d_in[4];
    const float* Wo     = (const float*)d_in[5];
    const float* ln1g   = (const float*)d_in[6];
    const float* ln1b   = (const float*)d_in[7];
    const float* W1     = (const float*)d_in[8];
    const float* b1     = (const float*)d_in[9];
    const float* W2     = (const float*)d_in[10];
    const float* b2     = (const float*)d_in[11];
    const float* ln2g   = (const float*)d_in[12];
    const float* ln2b   = (const float*)d_in[13];
    float* out = (float*)d_out;

    int8_t *x8a,*x8b,*c8a,*c8b,*y8a,*y8b,*h8a,*h8b,*w8a,*w8b;
    float *sx,*sc,*sy,*shs,*swf,*ctx,*x2,*hf;
    unsigned* swb;
    __nv_bfloat16 *qh,*ql;
    cudaGetSymbolAddress((void**)&x8a, g_x8a); cudaGetSymbolAddress((void**)&x8b, g_x8b);
    cudaGetSymbolAddress((void**)&c8a, g_c8a); cudaGetSymbolAddress((void**)&c8b, g_c8b);
    cudaGetSymbolAddress((void**)&y8a, g_y8a); cudaGetSymbolAddress((void**)&y8b, g_y8b);
    cudaGetSymbolAddress((void**)&h8a, g_h8a); cudaGetSymbolAddress((void**)&h8b, g_h8b);
    cudaGetSymbolAddress((void**)&sx, g_sx);   cudaGetSymbolAddress((void**)&sc, g_sc);
    cudaGetSymbolAddress((void**)&sy, g_sy);   cudaGetSymbolAddress((void**)&shs, g_sh);
    cudaGetSymbolAddress((void**)&w8a, g_w8a); cudaGetSymbolAddress((void**)&w8b, g_w8b);
    cudaGetSymbolAddress((void**)&swb, g_swb); cudaGetSymbolAddress((void**)&swf, g_swf);
    cudaGetSymbolAddress((void**)&qh, g_qh);   cudaGetSymbolAddress((void**)&ql, g_ql);
    cudaGetSymbolAddress((void**)&ctx, g_ctx); cudaGetSymbolAddress((void**)&x2, g_x2);
    cudaGetSymbolAddress((void**)&hf, g_hf);

    cudaFuncSetAttribute(attn_tc, cudaFuncAttributeMaxDynamicSharedMemorySize,
                         AT_SMEM_BYTES);
    cudaFuncSetAttribute(gemm_i8, cudaFuncAttributeMaxDynamicSharedMemorySize,
                         I8_SMEM);

    const int M = MROWS;

    // ---- weight quantization (per launch; deterministic) ----
    zero_scales<<<(NSCALE + 255) / 256, 256>>>(swb, NSCALE);
    colmax_w<<<dim3(DD/256, 8), 256>>>(Wq, swb + SQKV,          DD, DD);
    colmax_w<<<dim3(DD/256, 8), 256>>>(Wk, swb + SQKV + DD,     DD, DD);
    colmax_w<<<dim3(DD/256, 8), 256>>>(Wv, swb + SQKV + 2*DD,   DD, DD);
    colmax_w<<<dim3(DD/256, 8), 256>>>(Wo, swb + SWO,           DD, DD);
    colmax_w<<<dim3(FF/256, 8), 256>>>(W1, swb + SW1,           DD, FF);
    colmax_w<<<dim3(DD/256, 8), 256>>>(W2, swb + SW2,           FF, DD);
    finalize_scales<<<(NSCALE + 255) / 256, 256>>>(swb, swf, NSCALE);
    quantsplit_w<<<dim3(DD/32, DD/32), 256>>>(Wq, w8a + OQKV,            w8b + OQKV,            swf + SQKV,        DD, DD);
    quantsplit_w<<<dim3(DD/32, DD/32), 256>>>(Wk, w8a + OQKV + DD*DD,    w8b + OQKV + DD*DD,    swf + SQKV + DD,   DD, DD);
    quantsplit_w<<<dim3(DD/32, DD/32), 256>>>(Wv, w8a + OQKV + 2*DD*DD,  w8b + OQKV + 2*DD*DD,  swf + SQKV + 2*DD, DD, DD);
    quantsplit_w<<<dim3(DD/32, DD/32), 256>>>(Wo, w8a + OWO,             w8b + OWO,             swf + SWO,         DD, DD);
    quantsplit_w<<<dim3(FF/32, DD/32), 256>>>(W1, w8a + OW1,             w8b + OW1,             swf + SW1,         DD, FF);
    quantsplit_w<<<dim3(DD/32, FF/32), 256>>>(W2, w8a + OW2,             w8b + OW2,             swf + SW2,         FF, DD);

    // ---- block ----
    ln_quant<<<M, 256>>>(hidden, ln1g, ln1b, x8a, x8b, sx);
    gemm_i8<<<dim3(QKVD/128, M/128), 512, I8_SMEM>>>(
        x8a, x8b, sx, w8a + OQKV, w8b + OQKV, swf + SQKV,
        nullptr, nullptr, nullptr, qh, ql, M, QKVD, DD, 0);
    attn_tc<<<dim3(SS/128, BB*HH), 256, AT_SMEM_BYTES>>>(qh, ql, amask, ctx);
    quant_rows<<<M, 256>>>(ctx, c8a, c8b, sc, DD);
    gemm_i8<<<dim3(DD/128, M/128), 512, I8_SMEM>>>(
        c8a, c8b, sc, w8a + OWO, w8b + OWO, swf + SWO,
        nullptr, hidden, x2, nullptr, nullptr, M, DD, DD, 0);
    ln_quant<<<M, 256>>>(x2, ln2g, ln2b, y8a, y8b, sy);
    gemm_i8<<<dim3(FF/128, M/128), 512, I8_SMEM>>>(
        y8a, y8b, sy, w8a + OW1, w8b + OW1, swf + SW1,
        b1, nullptr, hf, nullptr, nullptr, M, FF, DD, 1);
    quant_rows<<<M, 256>>>(hf, h8a, h8b, shs, FF);
    gemm_i8<<<dim3(DD/128, M/128), 512, I8_SMEM>>>(
        h8a, h8b, shs, w8a + OW2, w8b + OW2, swf + SW2,
        b2, x2, out, nullptr, nullptr, M, DD, FF, 0);
}

// round 8
// speedup vs baseline: 2.6860x; 2.6860x over previous
#include <cuda_runtime.h>
#include <cuda_bf16.h>
#include <cuda_fp16.h>
#include <math.h>
#include <stdint.h>

#define BB 4
#define SS 2048
#define DD 1024
#define FF 4096
#define HH 16
#define QKVD (3*DD)
#define INV_SCALE 0.125f
#define NEGBIG -1e30f
#define MROWS (BB*SS)
#define M1 (DD*DD)

// ---------------- scratch ------------------------------------------------------
__device__ __nv_bfloat16 g_xh [MROWS*DD];
__device__ __nv_bfloat16 g_xl [MROWS*DD];
__device__ __nv_bfloat16 g_qh [(size_t)MROWS*QKVD];
__device__ __nv_bfloat16 g_ql [(size_t)MROWS*QKVD];
__device__ __nv_bfloat16 g_ch [MROWS*DD];
__device__ __nv_bfloat16 g_cl [MROWS*DD];
__device__ float         g_x2 [MROWS*DD];
__device__ __half        g_y16[MROWS*DD];
__device__ __half        g_h16[(size_t)MROWS*FF];
__device__ __nv_bfloat16 g_wT [8*M1];            // QKV hi/lo + Wo hi/lo
__device__ __half        g_w1h[(size_t)FF*DD], g_w1l[(size_t)FF*DD];  // [FF,DD]
__device__ __half        g_w2h[(size_t)DD*FF], g_w2l[(size_t)DD*FF];  // [DD,FF]

// ---------------- helpers ------------------------------------------------------
__device__ __forceinline__ uint32_t split_pack(float a, float b, uint32_t& lo) {
    __nv_bfloat16 ha = __float2bfloat16(a), hb = __float2bfloat16(b);
    __nv_bfloat16 la = __float2bfloat16(a - __bfloat162float(ha));
    __nv_bfloat16 lb = __float2bfloat16(b - __bfloat162float(hb));
    lo = (uint32_t)__bfloat16_as_ushort(la) | ((uint32_t)__bfloat16_as_ushort(lb) << 16);
    return (uint32_t)__bfloat16_as_ushort(ha) | ((uint32_t)__bfloat16_as_ushort(hb) << 16);
}
__device__ __forceinline__ void hmma(float* d, uint32_t a0, uint32_t a1,
                                     uint32_t a2, uint32_t a3,
                                     uint32_t b0, uint32_t b1) {
    asm volatile("mma.sync.aligned.m16n8k16.row.col.f32.bf16.bf16.f32 "
                 "{%0,%1,%2,%3}, {%4,%5,%6,%7}, {%8,%9}, {%0,%1,%2,%3};"
                 : "+f"(d[0]), "+f"(d[1]), "+f"(d[2]), "+f"(d[3])
                 : "r"(a0), "r"(a1), "r"(a2), "r"(a3), "r"(b0), "r"(b1));
}
__device__ __forceinline__ void hmma16(float* d, uint32_t a0, uint32_t a1,
                                       uint32_t a2, uint32_t a3,
                                       uint32_t b0, uint32_t b1) {
    asm volatile("mma.sync.aligned.m16n8k16.row.col.f32.f16.f16.f32 "
                 "{%0,%1,%2,%3}, {%4,%5,%6,%7}, {%8,%9}, {%0,%1,%2,%3};"
                 : "+f"(d[0]), "+f"(d[1]), "+f"(d[2]), "+f"(d[3])
                 : "r"(a0), "r"(a1), "r"(a2), "r"(a3), "r"(b0), "r"(b1));
}
__device__ __forceinline__ uint32_t s2u(const void* p) {
    return (uint32_t)__cvta_generic_to_shared(p);
}
__device__ __forceinline__ void cp16(uint32_t dst, const void* src) {
    asm volatile("cp.async.ca.shared.global [%0], [%1], 16;" :: "r"(dst), "l"(src));
}
__device__ __forceinline__ void cp_commit() { asm volatile("cp.async.commit_group;"); }
__device__ __forceinline__ void cp_wait0()  { asm volatile("cp.async.wait_group 0;"); }
__device__ __forceinline__ void cp_wait1()  { asm volatile("cp.async.wait_group 1;"); }
__device__ __forceinline__ void ldm4(uint32_t addr, uint32_t& r0, uint32_t& r1,
                                     uint32_t& r2, uint32_t& r3) {
    asm volatile("ldmatrix.sync.aligned.m8n8.x4.shared.b16 {%0,%1,%2,%3}, [%4];"
                 : "=r"(r0), "=r"(r1), "=r"(r2), "=r"(r3) : "r"(addr));
}
__device__ __forceinline__ void ldm4t(uint32_t addr, uint32_t& r0, uint32_t& r1,
                                      uint32_t& r2, uint32_t& r3) {
    asm volatile("ldmatrix.sync.aligned.m8n8.x4.trans.shared.b16 {%0,%1,%2,%3}, [%4];"
                 : "=r"(r0), "=r"(r1), "=r"(r2), "=r"(r3) : "r"(addr));
}

// ---------------- LayerNorm with split bf16 output -----------------------------
__global__ __launch_bounds__(256)
void ln_split(const float* __restrict__ x, const float* __restrict__ g,
              const float* __restrict__ b, __nv_bfloat16* __restrict__ outH,
              __nv_bfloat16* __restrict__ outL)
{
    int row = blockIdx.x;
    int tid = threadIdx.x;
    const float* xr = x + (size_t)row * DD;
    float4 v = *reinterpret_cast<const float4*>(xr + tid * 4);
    float s  = v.x + v.y + v.z + v.w;
    float sq = v.x*v.x + v.y*v.y + v.z*v.z + v.w*v.w;
    #pragma unroll
    for (int o = 16; o > 0; o >>= 1) {
        s  += __shfl_xor_sync(0xffffffffu, s,  o);
        sq += __shfl_xor_sync(0xffffffffu, sq, o);
    }
    __shared__ float ws[8], wq[8];
    __shared__ float smean, srstd;
    int wid = tid >> 5, lane = tid & 31;
    if (lane == 0) { ws[wid] = s; wq[wid] = sq; }
    __syncthreads();
    if (tid == 0) {
        float S = 0.f, Q = 0.f;
        #pragma unroll
        for (int i = 0; i < 8; i++) { S += ws[i]; Q += wq[i]; }
        float mean = S * (1.f / DD);
        float var  = fmaxf(Q * (1.f / DD) - mean * mean, 0.f);
        smean = mean;
        srstd = rsqrtf(var + 1e-12f);
    }
    __syncthreads();
    float mean = smean, rstd = srstd;
    float4 gv = *reinterpret_cast<const float4*>(g + tid * 4);
    float4 bv = *reinterpret_cast<const float4*>(b + tid * 4);
    float o0 = (v.x - mean) * rstd * gv.x + bv.x;
    float o1 = (v.y - mean) * rstd * gv.y + bv.y;
    float o2 = (v.z - mean) * rstd * gv.z + bv.z;
    float o3 = (v.w - mean) * rstd * gv.w + bv.w;
    uint32_t l0, l1;
    uint32_t h0 = split_pack(o0, o1, l0);
    uint32_t h1 = split_pack(o2, o3, l1);
    size_t o = (size_t)row * DD + tid * 4;
    *reinterpret_cast<uint2*>(outH + o) = make_uint2(h0, h1);
    *reinterpret_cast<uint2*>(outL + o) = make_uint2(l0, l1);
}

// ---------------- LayerNorm with single fp16 output -----------------------------
__global__ __launch_bounds__(256)
void ln_f16(const float* __restrict__ x, const float* __restrict__ g,
            const float* __restrict__ b, __half* __restrict__ out16)
{
    int row = blockIdx.x;
    int tid = threadIdx.x;
    const float* xr = x + (size_t)row * DD;
    float4 v = *reinterpret_cast<const float4*>(xr + tid * 4);
    float s  = v.x + v.y + v.z + v.w;
    float sq = v.x*v.x + v.y*v.y + v.z*v.z + v.w*v.w;
    #pragma unroll
    for (int o = 16; o > 0; o >>= 1) {
        s  += __shfl_xor_sync(0xffffffffu, s,  o);
        sq += __shfl_xor_sync(0xffffffffu, sq, o);
    }
    __shared__ float ws[8], wq[8];
    __shared__ float smean, srstd;
    int wid = tid >> 5, lane = tid & 31;
    if (lane == 0) { ws[wid] = s; wq[wid] = sq; }
    __syncthreads();
    if (tid == 0) {
        float S = 0.f, Q = 0.f;
        #pragma unroll
        for (int i = 0; i < 8; i++) { S += ws[i]; Q += wq[i]; }
        float mean = S * (1.f / DD);
        float var  = fmaxf(Q * (1.f / DD) - mean * mean, 0.f);
        smean = mean;
        srstd = rsqrtf(var + 1e-12f);
    }
    __syncthreads();
    float mean = smean, rstd = srstd;
    float4 gv = *reinterpret_cast<const float4*>(g + tid * 4);
    float4 bv = *reinterpret_cast<const float4*>(b + tid * 4);
    __half2 h0 = __floats2half2_rn((v.x - mean) * rstd * gv.x + bv.x,
                                   (v.y - mean) * rstd * gv.y + bv.y);
    __half2 h1 = __floats2half2_rn((v.z - mean) * rstd * gv.z + bv.z,
                                   (v.w - mean) * rstd * gv.w + bv.w);
    uint2 pk = make_uint2(*reinterpret_cast<uint32_t*>(&h0),
                          *reinterpret_cast<uint32_t*>(&h1));
    *reinterpret_cast<uint2*>(out16 + (size_t)row * DD + tid * 4) = pk;
}

// ---------------- weight transpose + bf16 split --------------------------------
__global__ __launch_bounds__(256)
void transsplit(const float* __restrict__ W, __nv_bfloat16* __restrict__ hiT,
                __nv_bfloat16* __restrict__ loT, int K, int N)
{
    __shared__ float tile[32][33];
    int n0 = blockIdx.x * 32, k0 = blockIdx.y * 32;
    int tx = threadIdx.x & 31, ty = threadIdx.x >> 5;
    for (int j = ty; j < 32; j += 8)
        tile[j][tx] = W[(size_t)(k0 + j) * N + n0 + tx];
    __syncthreads();
    for (int j = ty; j < 32; j += 8) {
        float x = tile[tx][j];
        __nv_bfloat16 h = __float2bfloat16(x);
        __nv_bfloat16 l = __float2bfloat16(x - __bfloat162float(h));
        size_t o = (size_t)(n0 + j) * K + k0 + tx;
        hiT[o] = h; loT[o] = l;
    }
}

// ---------------- weight transpose + fp16 split --------------------------------
__global__ __launch_bounds__(256)
void transsplit16(const float* __restrict__ W, __half* __restrict__ hiT,
                  __half* __restrict__ loT, int K, int N)
{
    __shared__ float tile[32][33];
    int n0 = blockIdx.x * 32, k0 = blockIdx.y * 32;
    int tx = threadIdx.x & 31, ty = threadIdx.x >> 5;
    for (int j = ty; j < 32; j += 8)
        tile[j][tx] = W[(size_t)(k0 + j) * N + n0 + tx];
    __syncthreads();
    for (int j = ty; j < 32; j += 8) {
        float x = tile[tx][j];
        __half h = __float2half_rn(x);
        __half l = __float2half_rn(x - __half2float(h));
        size_t o = (size_t)(n0 + j) * K + k0 + tx;
        hiT[o] = h; loT[o] = l;
    }
}

// ---------------- bf16x3 HMMA GEMM: 256x128 tile, 512 threads, 2-stage ----------
#define ASTRIDE 40
#define A_PLANE (256*ASTRIDE)
#define B_PLANE (128*ASTRIDE)
#define STG_HALVES (2*A_PLANE + 2*B_PLANE)
#define GT_SMEM_BYTES (2*STG_HALVES*2)

__global__ __launch_bounds__(512, 1)
void gemm_bf(const __nv_bfloat16* __restrict__ Ah, const __nv_bfloat16* __restrict__ Al,
             const __nv_bfloat16* __restrict__ Bh, const __nv_bfloat16* __restrict__ Bl,
             const float* __restrict__ res, float* __restrict__ outF,
             __nv_bfloat16* __restrict__ outH, __nv_bfloat16* __restrict__ outL,
             int M, int N, int K)
{
    extern __shared__ uint16_t sh[];
    uint32_t sb = s2u(sh);
    int tid = threadIdx.x;
    int wid = tid >> 5, lane = tid & 31;
    int g = lane >> 2, tg = lane & 3;
    int q8 = lane >> 3, e8 = lane & 7;
    int warp_m = wid & 3, warp_n = wid >> 2;
    int m0 = blockIdx.y * 256, n0 = blockIdx.x * 128;

    float acc[4][4][4];
    #pragma unroll
    for (int mt = 0; mt < 4; mt++)
        #pragma unroll
        for (int nt = 0; nt < 4; nt++)
            #pragma unroll
            for (int c = 0; c < 4; c++) acc[mt][nt][c] = 0.f;

    const __nv_bfloat16* gp[6];
    uint32_t so[6];
    #pragma unroll
    for (int u = 0; u < 6; u++) {
        int f = tid + u * 512;
        if (f < 2048) {
            int plane = f >> 10, fr = f & 1023;
            int row = fr >> 2, c = (fr & 3) << 3;
            gp[u] = (plane ? Al : Ah) + (size_t)(m0 + row) * K + c;
            so[u] = (uint32_t)(plane * A_PLANE + row * ASTRIDE + c) * 2;
        } else {
            int fb = f - 2048;
            int plane = fb >> 9, fr = fb & 511;
            int row = fr >> 2, c = (fr & 3) << 3;
            gp[u] = (plane ? Bl : Bh) + (size_t)(n0 + row) * K + c;
            so[u] = (uint32_t)(2 * A_PLANE + plane * B_PLANE + row * ASTRIDE + c) * 2;
        }
    }
    const int T = K >> 5;

    auto issue = [&](int t) {
        uint32_t st = sb + (uint32_t)(t & 1) * (STG_HALVES * 2);
        int k0 = t << 5;
        #pragma unroll
        for (int u = 0; u < 6; u++) cp16(st + so[u], gp[u] + k0);
        cp_commit();
    };

    issue(0);

    uint32_t aoff[4], boff[2];
    #pragma unroll
    for (int mt = 0; mt < 4; mt++)
        aoff[mt] = (uint32_t)((warp_m * 64 + mt * 16 + e8 + (q8 & 1) * 8) * ASTRIDE
                              + (q8 >> 1) * 8);
    #pragma unroll
    for (int p = 0; p < 2; p++)
        boff[p] = (uint32_t)((warp_n * 32 + (2 * p + (q8 >> 1)) * 8 + e8) * ASTRIDE
                             + (q8 & 1) * 8);

    for (int t = 0; t < T; t++) {
        cp_wait0();
        __syncthreads();
        if (t + 1 < T) issue(t + 1);

        uint32_t st = sb + (uint32_t)(t & 1) * (STG_HALVES * 2);
        #pragma unroll
        for (int ks = 0; ks < 32; ks += 16) {
            uint32_t ahi[4][4], alo[4][4];
            #pragma unroll
            for (int mt = 0; mt < 4; mt++) {
                ldm4(st + (aoff[mt] + ks) * 2,
                     ahi[mt][0], ahi[mt][1], ahi[mt][2], ahi[mt][3]);
                ldm4(st + (A_PLANE + aoff[mt] + ks) * 2,
                     alo[mt][0], alo[mt][1], alo[mt][2], alo[mt][3]);
            }
            #pragma unroll
            for (int p = 0; p < 2; p++) {
                uint32_t bh0, bh1, bh2, bh3, bl0, bl1, bl2, bl3;
                ldm4(st + (2 * A_PLANE + boff[p] + ks) * 2, bh0, bh1, bh2, bh3);
                ldm4(st + (2 * A_PLANE + B_PLANE + boff[p] + ks) * 2, bl0, bl1, bl2, bl3);
                int ntA = 2 * p, ntB = ntA + 1;
                #pragma unroll
                for (int mt = 0; mt < 4; mt++) {
                    hmma(acc[mt][ntA], ahi[mt][0], ahi[mt][1], ahi[mt][2], ahi[mt][3], bh0, bh1);
                    hmma(acc[mt][ntA], ahi[mt][0], ahi[mt][1], ahi[mt][2], ahi[mt][3], bl0, bl1);
                    hmma(acc[mt][ntA], alo[mt][0], alo[mt][1], alo[mt][2], alo[mt][3], bh0, bh1);
                    hmma(acc[mt][ntB], ahi[mt][0], ahi[mt][1], ahi[mt][2], ahi[mt][3], bh2, bh3);
                    hmma(acc[mt][ntB], ahi[mt][0], ahi[mt][1], ahi[mt][2], ahi[mt][3], bl2, bl3);
                    hmma(acc[mt][ntB], alo[mt][0], alo[mt][1], alo[mt][2], alo[mt][3], bh2, bh3);
                }
            }
        }
    }

    #pragma unroll
    for (int mt = 0; mt < 4; mt++) {
        #pragma unroll
        for (int nt = 0; nt < 4; nt++) {
            int row = m0 + warp_m * 64 + mt * 16 + g;
            int col = n0 + warp_n * 32 + nt * 8 + 2 * tg;
            #pragma unroll
            for (int half = 0; half < 2; half++) {
                int r = row + half * 8;
                float v0 = acc[mt][nt][half * 2 + 0];
                float v1 = acc[mt][nt][half * 2 + 1];
                size_t o = (size_t)r * N + col;
                if (outF) {
                    if (res) {
                        float2 rv = *reinterpret_cast<const float2*>(res + o);
                        v0 += rv.x; v1 += rv.y;
                    }
                    *reinterpret_cast<float2*>(outF + o) = make_float2(v0, v1);
                } else {
                    uint32_t lo;
                    uint32_t hi = split_pack(v0, v1, lo);
                    *reinterpret_cast<uint32_t*>(outH + o) = hi;
                    *reinterpret_cast<uint32_t*>(outL + o) = lo;
                }
            }
        }
    }
}

// ---------------- fp16 2-pass GEMM: A single plane, B hi/lo ---------------------
#define F16_STG (A_PLANE + 2*B_PLANE)
#define F16_SMEM (2*F16_STG*2)

__global__ __launch_bounds__(512, 1)
void gemm_f16(const __half* __restrict__ A,
              const __half* __restrict__ Bh, const __half* __restrict__ Bl,
              const float* __restrict__ bias, const float* __restrict__ res,
              float* __restrict__ outF, __half* __restrict__ out16,
              int M, int N, int K, int act)
{
    extern __shared__ uint16_t sh[];
    uint32_t sb = s2u(sh);
    int tid = threadIdx.x;
    int wid = tid >> 5, lane = tid & 31;
    int g = lane >> 2, tg = lane & 3;
    int q8 = lane >> 3, e8 = lane & 7;
    int warp_m = wid & 3, warp_n = wid >> 2;
    int m0 = blockIdx.y * 256, n0 = blockIdx.x * 128;

    float acc[4][4][4];
    #pragma unroll
    for (int mt = 0; mt < 4; mt++)
        #pragma unroll
        for (int nt = 0; nt < 4; nt++)
            #pragma unroll
            for (int c = 0; c < 4; c++) acc[mt][nt][c] = 0.f;

    // cp.async: A 1024 + B 1024 chunks per stage -> 4/thread
    const __half* gp[4];
    uint32_t so[4];
    #pragma unroll
    for (int u = 0; u < 4; u++) {
        int f = tid + u * 512;
        if (f < 1024) {
            int row = f >> 2, c = (f & 3) << 3;
            gp[u] = A + (size_t)(m0 + row) * K + c;
            so[u] = (uint32_t)(row * ASTRIDE + c) * 2;
        } else {
            int fb = f - 1024;
            int plane = fb >> 9, fr = fb & 511;
            int row = fr >> 2, c = (fr & 3) << 3;
            gp[u] = (plane ? Bl : Bh) + (size_t)(n0 + row) * K + c;
            so[u] = (uint32_t)(A_PLANE + plane * B_PLANE + row * ASTRIDE + c) * 2;
        }
    }
    const int T = K >> 5;

    auto issue = [&](int t) {
        uint32_t st = sb + (uint32_t)(t & 1) * (F16_STG * 2);
        int k0 = t << 5;
        #pragma unroll
        for (int u = 0; u < 4; u++) cp16(st + so[u], gp[u] + k0);
        cp_commit();
    };

    issue(0);

    uint32_t aoff[4], boff[2];
    #pragma unroll
    for (int mt = 0; mt < 4; mt++)
        aoff[mt] = (uint32_t)((warp_m * 64 + mt * 16 + e8 + (q8 & 1) * 8) * ASTRIDE
                              + (q8 >> 1) * 8);
    #pragma unroll
    for (int p = 0; p < 2; p++)
        boff[p] = (uint32_t)((warp_n * 32 + (2 * p + (q8 >> 1)) * 8 + e8) * ASTRIDE
                             + (q8 & 1) * 8);

    for (int t = 0; t < T; t++) {
        cp_wait0();
        __syncthreads();
        if (t + 1 < T) issue(t + 1);

        uint32_t st = sb + (uint32_t)(t & 1) * (F16_STG * 2);
        #pragma unroll
        for (int ks = 0; ks < 32; ks += 16) {
            uint32_t af[4][4];
            #pragma unroll
            for (int mt = 0; mt < 4; mt++)
                ldm4(st + (aoff[mt] + ks) * 2,
                     af[mt][0], af[mt][1], af[mt][2], af[mt][3]);
            #pragma unroll
            for (int p = 0; p < 2; p++) {
                uint32_t bh0, bh1, bh2, bh3, bl0, bl1, bl2, bl3;
                ldm4(st + (A_PLANE + boff[p] + ks) * 2, bh0, bh1, bh2, bh3);
                ldm4(st + (A_PLANE + B_PLANE + boff[p] + ks) * 2, bl0, bl1, bl2, bl3);
                int ntA = 2 * p, ntB = ntA + 1;
                #pragma unroll
                for (int mt = 0; mt < 4; mt++) {
                    hmma16(acc[mt][ntA], af[mt][0], af[mt][1], af[mt][2], af[mt][3], bh0, bh1);
                    hmma16(acc[mt][ntA], af[mt][0], af[mt][1], af[mt][2], af[mt][3], bl0, bl1);
                    hmma16(acc[mt][ntB], af[mt][0], af[mt][1], af[mt][2], af[mt][3], bh2, bh3);
                    hmma16(acc[mt][ntB], af[mt][0], af[mt][1], af[mt][2], af[mt][3], bl2, bl3);
                }
            }
        }
    }

    #pragma unroll
    for (int mt = 0; mt < 4; mt++) {
        #pragma unroll
        for (int nt = 0; nt < 4; nt++) {
            int row = m0 + warp_m * 64 + mt * 16 + g;
            int col = n0 + warp_n * 32 + nt * 8 + 2 * tg;
            #pragma unroll
            for (int half = 0; half < 2; half++) {
                int r = row + half * 8;
                float v0 = acc[mt][nt][half * 2 + 0];
                float v1 = acc[mt][nt][half * 2 + 1];
                if (bias) { v0 += bias[col]; v1 += bias[col + 1]; }
                if (act) {
                    v0 = v0 / (1.f + __expf(-v0));
                    v1 = v1 / (1.f + __expf(-v1));
                }
                size_t o = (size_t)r * N + col;
                if (outF) {
                    if (res) {
                        float2 rv = *reinterpret_cast<const float2*>(res + o);
                        v0 += rv.x; v1 += rv.y;
                    }
                    *reinterpret_cast<float2*>(outF + o) = make_float2(v0, v1);
                } else {
                    __half2 hv = __floats2half2_rn(v0, v1);
                    *reinterpret_cast<uint32_t*>(out16 + o) =
                        *reinterpret_cast<uint32_t*>(&hv);
                }
            }
        }
    }
}

// ---------------- tensor-core flash attention: 128 q-rows, 256 threads ----------
#define AT_STRIDE 72
#define QPB (128*AT_STRIDE*2)
#define KPB (64*AT_STRIDE*2)
#define KV_BASE (2*QPB)
#define AT_SMEM_BYTES (KV_BASE + 8*KPB + 3*64*4)

__global__ __launch_bounds__(256)
void attn_tc(const __nv_bfloat16* __restrict__ qh, const __nv_bfloat16* __restrict__ ql,
             const int* __restrict__ amask,
             __nv_bfloat16* __restrict__ ctxh, __nv_bfloat16* __restrict__ ctxl)
{
    extern __shared__ uint16_t ash[];
    uint32_t sb = s2u(ash);
    float* koff = reinterpret_cast<float*>((char*)ash + KV_BASE + 8 * KPB);

    int tid = threadIdx.x;
    int lane = tid & 31, w = tid >> 5;
    int g = lane >> 2, tg = lane & 3;
    int q8 = lane >> 3, e8 = lane & 7;
    int bh = blockIdx.y;
    int b = bh >> 4, h = bh & 15;
    int qt = gridDim.x - 1 - blockIdx.x;
    int q0 = qt * 128;
    const size_t rowbase = (size_t)b * SS;
    const int hoff = h * 64;
    const int ktmax = 2 * qt + 1;

    const __nv_bfloat16* qgp[8]; uint32_t qso[8];
    #pragma unroll
    for (int u = 0; u < 8; u++) {
        int f = tid + u * 256;
        int plane = f >> 10, fr = f & 1023;
        int row = fr >> 3, c = (fr & 7) << 3;
        qgp[u] = (plane ? ql : qh) + (rowbase + q0 + row) * QKVD + hoff + c;
        qso[u] = (uint32_t)(plane * (QPB / 2) + row * AT_STRIDE + c) * 2;
    }
    const __nv_bfloat16* kvgp[8]; uint32_t kvso[8]; int kvrow[8];
    #pragma unroll
    for (int u = 0; u < 8; u++) {
        int f = tid + u * 256;
        int plane = f >> 9, fr = f & 511;
        int row = fr >> 3, c = (fr & 7) << 3;
        const __nv_bfloat16* base = (plane == 0) ? qh + DD : (plane == 1) ? ql + DD
                                   : (plane == 2) ? qh + 2 * DD : ql + 2 * DD;
        kvgp[u] = base + rowbase * QKVD + hoff + c;
        kvrow[u] = row;
        kvso[u] = (uint32_t)KV_BASE + (uint32_t)(plane * (KPB / 2) + row * AT_STRIDE + c) * 2;
    }

    auto issueKV = [&](int kt) {
        uint32_t st = sb + (uint32_t)(kt & 1) * (4 * KPB);
        int k0 = kt * 64;
        #pragma unroll
        for (int u = 0; u < 8; u++)
            cp16(st + kvso[u], kvgp[u] + (size_t)(k0 + kvrow[u]) * QKVD);
        cp_commit();
        if (tid < 64)
            koff[(kt % 3) * 64 + tid] = (amask[b * SS + k0 + tid] == 1) ? 0.f : NEGBIG;
    };

    #pragma unroll
    for (int u = 0; u < 8; u++) cp16(sb + qso[u], qgp[u]);
    cp_commit();
    issueKV(0);
    issueKV(1);
    cp_wait1();
    __syncthreads();

    uint32_t qfh[4][4], qfl[4][4];
    uint32_t qoffb = (uint32_t)((w * 16 + e8 + (q8 & 1) * 8) * AT_STRIDE + (q8 >> 1) * 8);
    #pragma unroll
    for (int kt = 0; kt < 4; kt++) {
        ldm4(sb + (qoffb + 16 * kt) * 2, qfh[kt][0], qfh[kt][1], qfh[kt][2], qfh[kt][3]);
        ldm4(sb + QPB + (qoffb + 16 * kt) * 2,
             qfl[kt][0], qfl[kt][1], qfl[kt][2], qfl[kt][3]);
    }

    uint32_t kboff[4], vboff[4];
    #pragma unroll
    for (int p = 0; p < 4; p++) {
        kboff[p] = (uint32_t)(((2 * p + (q8 >> 1)) * 8 + e8) * AT_STRIDE + (q8 & 1) * 8);
        vboff[p] = (uint32_t)(((q8 & 1) * 8 + e8) * AT_STRIDE + (2 * p + (q8 >> 1)) * 8);
    }

    float o[8][4];
    #pragma unroll
    for (int nt = 0; nt < 8; nt++)
        #pragma unroll
        for (int c = 0; c < 4; c++) o[nt][c] = 0.f;
    float m0v = NEGBIG, m1v = NEGBIG, l0 = 0.f, l1 = 0.f;
    int r0g = q0 + w * 16 + g, r1g = r0g + 8;

    for (int kt_g = 0; kt_g <= ktmax; kt_g++) {
        int k0 = kt_g * 64;
        if (kt_g == ktmax) cp_wait0(); else cp_wait1();
        __syncthreads();

        uint32_t st = sb + (uint32_t)(kt_g & 1) * (4 * KPB);
        uint32_t stK  = st + KV_BASE;
        uint32_t stKl = stK + KPB;
        uint32_t stV  = stK + 2 * KPB;
        uint32_t stVl = stK + 3 * KPB;
        const float* kofft = koff + (kt_g % 3) * 64;

        float s[8][4];
        #pragma unroll
        for (int nt = 0; nt < 8; nt++)
            #pragma unroll
            for (int c = 0; c < 4; c++) s[nt][c] = 0.f;
        #pragma unroll
        for (int kt = 0; kt < 4; kt++) {
            #pragma unroll
            for (int p = 0; p < 4; p++) {
                uint32_t bh0, bh1, bh2, bh3, bl0, bl1, bl2, bl3;
                ldm4(stK  + (kboff[p] + 16 * kt) * 2, bh0, bh1, bh2, bh3);
                ldm4(stKl + (kboff[p] + 16 * kt) * 2, bl0, bl1, bl2, bl3);
                int ntA = 2 * p, ntB = ntA + 1;
                hmma(s[ntA], qfh[kt][0], qfh[kt][1], qfh[kt][2], qfh[kt][3], bh0, bh1);
                hmma(s[ntA], qfh[kt][0], qfh[kt][1], qfh[kt][2], qfh[kt][3], bl0, bl1);
                hmma(s[ntA], qfl[kt][0], qfl[kt][1], qfl[kt][2], qfl[kt][3], bh0, bh1);
                hmma(s[ntB], qfh[kt][0], qfh[kt][1], qfh[kt][2], qfh[kt][3], bh2, bh3);
                hmma(s[ntB], qfh[kt][0], qfh[kt][1], qfh[kt][2], qfh[kt][3], bl2, bl3);
                hmma(s[ntB], qfl[kt][0], qfl[kt][1], qfl[kt][2], qfl[kt][3], bh2, bh3);
            }
        }

        float mx0 = NEGBIG, mx1 = NEGBIG;
        #pragma unroll
        for (int nt = 0; nt < 8; nt++) {
            int c0 = k0 + 8 * nt + 2 * tg;
            float kf0 = kofft[8 * nt + 2 * tg], kf1 = kofft[8 * nt + 2 * tg + 1];
            float v0 = s[nt][0] * INV_SCALE + kf0;
            float v1 = s[nt][1] * INV_SCALE + kf1;
            float v2 = s[nt][2] * INV_SCALE + kf0;
            float v3 = s[nt][3] * INV_SCALE + kf1;
            if (c0     > r0g) v0 = NEGBIG;
            if (c0 + 1 > r0g) v1 = NEGBIG;
            if (c0     > r1g) v2 = NEGBIG;
            if (c0 + 1 > r1g) v3 = NEGBIG;
            s[nt][0] = v0; s[nt][1] = v1; s[nt][2] = v2; s[nt][3] = v3;
            mx0 = fmaxf(mx0, fmaxf(v0, v1));
            mx1 = fmaxf(mx1, fmaxf(v2, v3));
        }
        mx0 = fmaxf(mx0, __shfl_xor_sync(0xffffffffu, mx0, 1));
        mx0 = fmaxf(mx0, __shfl_xor_sync(0xffffffffu, mx0, 2));
        mx1 = fmaxf(mx1, __shfl_xor_sync(0xffffffffu, mx1, 1));
        mx1 = fmaxf(mx1, __shfl_xor_sync(0xffffffffu, mx1, 2));

        float mn0 = fmaxf(m0v, mx0), mn1 = fmaxf(m1v, mx1);
        float al0 = __expf(m0v - mn0), al1 = __expf(m1v - mn1);
        m0v = mn0; m1v = mn1;
        l0 *= al0; l1 *= al1;

        #pragma unroll
        for (int nt = 0; nt < 8; nt++) {
            float p0 = __expf(s[nt][0] - m0v);
            float p1 = __expf(s[nt][1] - m0v);
            float p2 = __expf(s[nt][2] - m1v);
            float p3 = __expf(s[nt][3] - m1v);
            s[nt][0] = p0; s[nt][1] = p1; s[nt][2] = p2; s[nt][3] = p3;
            l0 += p0 + p1; l1 += p2 + p3;
        }
        #pragma unroll
        for (int nt = 0; nt < 8; nt++) {
            o[nt][0] *= al0; o[nt][1] *= al0;
            o[nt][2] *= al1; o[nt][3] *= al1;
        }

        #pragma unroll
        for (int ktP = 0; ktP < 4; ktP++) {
            int ntA = 2 * ktP, ntB = ntA + 1;
            uint32_t a0l, a1l, a2l, a3l;
            uint32_t a0h = split_pack(s[ntA][0], s[ntA][1], a0l);
            uint32_t a1h = split_pack(s[ntA][2], s[ntA][3], a1l);
            uint32_t a2h = split_pack(s[ntB][0], s[ntB][1], a2l);
            uint32_t a3h = split_pack(s[ntB][2], s[ntB][3], a3l);
            #pragma unroll
            for (int p = 0; p < 4; p++) {
                uint32_t bh0, bh1, bh2, bh3, bl0, bl1, bl2, bl3;
                ldm4t(stV  + (vboff[p] + 16 * ktP * AT_STRIDE) * 2, bh0, bh1, bh2, bh3);
                ldm4t(stVl + (vboff[p] + 16 * ktP * AT_STRIDE) * 2, bl0, bl1, bl2, bl3);
                int n2A = 2 * p, n2B = n2A + 1;
                hmma(o[n2A], a0h, a1h, a2h, a3h, bh0, bh1);
                hmma(o[n2A], a0l, a1l, a2l, a3l, bh0, bh1);
                hmma(o[n2A], a0h, a1h, a2h, a3h, bl0, bl1);
                hmma(o[n2B], a0h, a1h, a2h, a3h, bh2, bh3);
                hmma(o[n2B], a0l, a1l, a2l, a3l, bh2, bh3);
                hmma(o[n2B], a0h, a1h, a2h, a3h, bl2, bl3);
            }
        }

        __syncthreads();
        if (kt_g + 2 <= ktmax) issueKV(kt_g + 2);
    }

    l0 += __shfl_xor_sync(0xffffffffu, l0, 1);
    l0 += __shfl_xor_sync(0xffffffffu, l0, 2);
    l1 += __shfl_xor_sync(0xffffffffu, l1, 1);
    l1 += __shfl_xor_sync(0xffffffffu, l1, 2);
    float inv0 = 1.f / l0, inv1 = 1.f / l1;

    #pragma unroll
    for (int nt = 0; nt < 8; nt++) {
        int col = hoff + 8 * nt + 2 * tg;
        uint32_t lo0, lo1;
        uint32_t hi0 = split_pack(o[nt][0] * inv0, o[nt][1] * inv0, lo0);
        uint32_t hi1 = split_pack(o[nt][2] * inv1, o[nt][3] * inv1, lo1);
        size_t o0 = (rowbase + r0g) * DD + col;
        size_t o1 = (rowbase + r1g) * DD + col;
        *reinterpret_cast<uint32_t*>(ctxh + o0) = hi0;
        *reinterpret_cast<uint32_t*>(ctxl + o0) = lo0;
        *reinterpret_cast<uint32_t*>(ctxh + o1) = hi1;
        *reinterpret_cast<uint32_t*>(ctxl + o1) = lo1;
    }
}

// ---------------- host ---------------------------------------------------------
extern "C" void kernel_launch(void* const* d_in, const int* in_sizes, int n_in,
                              void* d_out, int out_size)
{
    const float* hidden = (const float*)d_in[0];
    const int*   amask  = (const int*)  d_in[1];
    const float* Wq     = (const float*)d_in[2];
    const float* Wk     = (const float*)d_in[3];
    const float* Wv     = (const float*)d_in[4];
    const float* Wo     = (const float*)d_in[5];
    const float* ln1g   = (const float*)d_in[6];
    const float* ln1b   = (const float*)d_in[7];
    const float* W1     = (const float*)d_in[8];
    const float* b1     = (const float*)d_in[9];
    const float* W2     = (const float*)d_in[10];
    const float* b2     = (const float*)d_in[11];
    const float* ln2g   = (const float*)d_in[12];
    const float* ln2b   = (const float*)d_in[13];
    float* out = (float*)d_out;

    __nv_bfloat16 *xh, *xl, *qh, *ql, *ch, *cl, *wT;
    __half *y16, *h16, *w1h, *w1l, *w2h, *w2l;
    float* x2;
    cudaGetSymbolAddress((void**)&xh, g_xh);
    cudaGetSymbolAddress((void**)&xl, g_xl);
    cudaGetSymbolAddress((void**)&qh, g_qh);
    cudaGetSymbolAddress((void**)&ql, g_ql);
    cudaGetSymbolAddress((void**)&ch, g_ch);
    cudaGetSymbolAddress((void**)&cl, g_cl);
    cudaGetSymbolAddress((void**)&x2, g_x2);
    cudaGetSymbolAddress((void**)&y16, g_y16);
    cudaGetSymbolAddress((void**)&h16, g_h16);
    cudaGetSymbolAddress((void**)&wT, g_wT);
    cudaGetSymbolAddress((void**)&w1h, g_w1h);
    cudaGetSymbolAddress((void**)&w1l, g_w1l);
    cudaGetSymbolAddress((void**)&w2h, g_w2h);
    cudaGetSymbolAddress((void**)&w2l, g_w2l);

    cudaFuncSetAttribute(attn_tc, cudaFuncAttributeMaxDynamicSharedMemorySize,
                         AT_SMEM_BYTES);
    cudaFuncSetAttribute(gemm_bf, cudaFuncAttributeMaxDynamicSharedMemorySize,
                         GT_SMEM_BYTES);
    cudaFuncSetAttribute(gemm_f16, cudaFuncAttributeMaxDynamicSharedMemorySize,
                         F16_SMEM);

    const int M = MROWS;

    // weight prep: QKV hi 0..3M1, lo 3..6M1; Wo hi 6M1, lo 7M1 (bf16);
    // W1/W2 fp16 hi/lo planes.
    transsplit<<<dim3(DD/32, DD/32), 256>>>(Wq, wT,          wT + 3*M1,  DD, DD);
    transsplit<<<dim3(DD/32, DD/32), 256>>>(Wk, wT + M1,     wT + 4*M1,  DD, DD);
    transsplit<<<dim3(DD/32, DD/32), 256>>>(Wv, wT + 2*M1,   wT + 5*M1,  DD, DD);
    transsplit<<<dim3(DD/32, DD/32), 256>>>(Wo, wT + 6*M1,   wT + 7*M1,  DD, DD);
    transsplit16<<<dim3(FF/32, DD/32), 256>>>(W1, w1h, w1l, DD, FF);
    transsplit16<<<dim3(DD/32, FF/32), 256>>>(W2, w2h, w2l, FF, DD);

    // LN1 -> split bf16
    ln_split<<<M, 256>>>(hidden, ln1g, ln1b, xh, xl);
    // fused QKV projection (bf16x3) -> split planes
    gemm_bf<<<dim3(QKVD/128, M/256), 512, GT_SMEM_BYTES>>>(
        xh, xl, wT, wT + 3*M1, nullptr, nullptr, qh, ql, M, QKVD, DD);
    // attention (bf16x3)
    attn_tc<<<dim3(SS/128, BB*HH), 256, AT_SMEM_BYTES>>>(qh, ql, amask, ch, cl);
    // output projection + residual (bf16x3) -> fp32 x2
    gemm_bf<<<dim3(DD/128, M/256), 512, GT_SMEM_BYTES>>>(
        ch, cl, wT + 6*M1, wT + 7*M1, hidden, x2, nullptr, nullptr, M, DD, DD);
    // LN2 -> fp16 single plane
    ln_f16<<<M, 256>>>(x2, ln2g, ln2b, y16);
    // FFN1 (fp16 2-pass, bias + SiLU) -> fp16 h
    gemm_f16<<<dim3(FF/128, M/256), 512, F16_SMEM>>>(
        y16, w1h, w1l, b1, nullptr, nullptr, h16, M, FF, DD, 1);
    // FFN2 (fp16 2-pass, bias + residual x2) -> fp32 out
    gemm_f16<<<dim3(DD/128, M/256), 512, F16_SMEM>>>(
        h16, w2h, w2l, b2, x2, out, nullptr, M, DD, FF, 0);
}

// round 9
// speedup vs baseline: 3.2167x; 1.1976x over previous
#include <cuda_runtime.h>
#include <cuda_bf16.h>
#include <cuda_fp16.h>
#include <math.h>
#include <stdint.h>

#define BB 4
#define SS 2048
#define DD 1024
#define FF 4096
#define HH 16
#define QKVD (3*DD)
#define INV_SCALE 0.125f
#define NEGBIG -1e30f
#define MROWS (BB*SS)
#define M1 (DD*DD)

// ---------------- scratch ------------------------------------------------------
__device__ __half g_x16 [MROWS*DD];
__device__ __half g_qkvh[(size_t)MROWS*QKVD];
__device__ __half g_qkvl[(size_t)MROWS*QKVD];
__device__ __half g_ctx16[MROWS*DD];
__device__ float  g_x2  [MROWS*DD];
__device__ __half g_y16 [MROWS*DD];
__device__ __half g_h16 [(size_t)MROWS*FF];
// weights fp16 hi/lo, [N,K]: QKV@0 (3M1), Wo@3M1 (M1), W1@4M1 (4M1), W2@8M1 (4M1)
__device__ __half g_wh[(size_t)12*M1];
__device__ __half g_wl[(size_t)12*M1];

// ---------------- helpers ------------------------------------------------------
__device__ __forceinline__ uint32_t pk16(float a, float b) {
    __half2 h = __floats2half2_rn(a, b);
    return *reinterpret_cast<uint32_t*>(&h);
}
__device__ __forceinline__ uint32_t split_pack16(float a, float b, uint32_t& lo) {
    __half ha = __float2half_rn(a), hb = __float2half_rn(b);
    __half la = __float2half_rn(a - __half2float(ha));
    __half lb = __float2half_rn(b - __half2float(hb));
    lo = (uint32_t)__half_as_ushort(la) | ((uint32_t)__half_as_ushort(lb) << 16);
    return (uint32_t)__half_as_ushort(ha) | ((uint32_t)__half_as_ushort(hb) << 16);
}
__device__ __forceinline__ void hmma16(float* d, uint32_t a0, uint32_t a1,
                                       uint32_t a2, uint32_t a3,
                                       uint32_t b0, uint32_t b1) {
    asm volatile("mma.sync.aligned.m16n8k16.row.col.f32.f16.f16.f32 "
                 "{%0,%1,%2,%3}, {%4,%5,%6,%7}, {%8,%9}, {%0,%1,%2,%3};"
                 : "+f"(d[0]), "+f"(d[1]), "+f"(d[2]), "+f"(d[3])
                 : "r"(a0), "r"(a1), "r"(a2), "r"(a3), "r"(b0), "r"(b1));
}
__device__ __forceinline__ uint32_t s2u(const void* p) {
    return (uint32_t)__cvta_generic_to_shared(p);
}
__device__ __forceinline__ void cp16(uint32_t dst, const void* src) {
    asm volatile("cp.async.ca.shared.global [%0], [%1], 16;" :: "r"(dst), "l"(src));
}
__device__ __forceinline__ void cp_commit() { asm volatile("cp.async.commit_group;"); }
__device__ __forceinline__ void cp_wait0()  { asm volatile("cp.async.wait_group 0;"); }
__device__ __forceinline__ void cp_wait1()  { asm volatile("cp.async.wait_group 1;"); }
__device__ __forceinline__ void ldm4(uint32_t addr, uint32_t& r0, uint32_t& r1,
                                     uint32_t& r2, uint32_t& r3) {
    asm volatile("ldmatrix.sync.aligned.m8n8.x4.shared.b16 {%0,%1,%2,%3}, [%4];"
                 : "=r"(r0), "=r"(r1), "=r"(r2), "=r"(r3) : "r"(addr));
}
__device__ __forceinline__ void ldm4t(uint32_t addr, uint32_t& r0, uint32_t& r1,
                                      uint32_t& r2, uint32_t& r3) {
    asm volatile("ldmatrix.sync.aligned.m8n8.x4.trans.shared.b16 {%0,%1,%2,%3}, [%4];"
                 : "=r"(r0), "=r"(r1), "=r"(r2), "=r"(r3) : "r"(addr));
}

// ---------------- LayerNorm -> single fp16 -------------------------------------
__global__ __launch_bounds__(256)
void ln_f16(const float* __restrict__ x, const float* __restrict__ g,
            const float* __restrict__ b, __half* __restrict__ out16)
{
    int row = blockIdx.x;
    int tid = threadIdx.x;
    const float* xr = x + (size_t)row * DD;
    float4 v = *reinterpret_cast<const float4*>(xr + tid * 4);
    float s  = v.x + v.y + v.z + v.w;
    float sq = v.x*v.x + v.y*v.y + v.z*v.z + v.w*v.w;
    #pragma unroll
    for (int o = 16; o > 0; o >>= 1) {
        s  += __shfl_xor_sync(0xffffffffu, s,  o);
        sq += __shfl_xor_sync(0xffffffffu, sq, o);
    }
    __shared__ float ws[8], wq[8];
    __shared__ float smean, srstd;
    int wid = tid >> 5, lane = tid & 31;
    if (lane == 0) { ws[wid] = s; wq[wid] = sq; }
    __syncthreads();
    if (tid == 0) {
        float S = 0.f, Q = 0.f;
        #pragma unroll
        for (int i = 0; i < 8; i++) { S += ws[i]; Q += wq[i]; }
        float mean = S * (1.f / DD);
        float var  = fmaxf(Q * (1.f / DD) - mean * mean, 0.f);
        smean = mean;
        srstd = rsqrtf(var + 1e-12f);
    }
    __syncthreads();
    float mean = smean, rstd = srstd;
    float4 gv = *reinterpret_cast<const float4*>(g + tid * 4);
    float4 bv = *reinterpret_cast<const float4*>(b + tid * 4);
    uint2 pk = make_uint2(
        pk16((v.x - mean) * rstd * gv.x + bv.x, (v.y - mean) * rstd * gv.y + bv.y),
        pk16((v.z - mean) * rstd * gv.z + bv.z, (v.w - mean) * rstd * gv.w + bv.w));
    *reinterpret_cast<uint2*>(out16 + (size_t)row * DD + tid * 4) = pk;
}

// ---------------- weight transpose + fp16 split --------------------------------
__global__ __launch_bounds__(256)
void transsplit16(const float* __restrict__ W, __half* __restrict__ hiT,
                  __half* __restrict__ loT, int K, int N)
{
    __shared__ float tile[32][33];
    int n0 = blockIdx.x * 32, k0 = blockIdx.y * 32;
    int tx = threadIdx.x & 31, ty = threadIdx.x >> 5;
    for (int j = ty; j < 32; j += 8)
        tile[j][tx] = W[(size_t)(k0 + j) * N + n0 + tx];
    __syncthreads();
    for (int j = ty; j < 32; j += 8) {
        float x = tile[tx][j];
        __half h = __float2half_rn(x);
        __half l = __float2half_rn(x - __half2float(h));
        size_t o = (size_t)(n0 + j) * K + k0 + tx;
        hiT[o] = h; loT[o] = l;
    }
}

// ---------------- fp16 2-pass GEMM: 256x128 tile, 512 threads, 2-stage ----------
#define ASTRIDE 40
#define A_PLANE (256*ASTRIDE)
#define B_PLANE (128*ASTRIDE)
#define F16_STG (A_PLANE + 2*B_PLANE)
#define F16_SMEM (2*F16_STG*2)

__global__ __launch_bounds__(512, 1)
void gemm_f16(const __half* __restrict__ A,
              const __half* __restrict__ Bh, const __half* __restrict__ Bl,
              const float* __restrict__ bias, const float* __restrict__ res,
              float* __restrict__ outF, __half* __restrict__ out16,
              __half* __restrict__ outH, __half* __restrict__ outL,
              int M, int N, int K, int act)
{
    extern __shared__ uint16_t sh[];
    uint32_t sb = s2u(sh);
    int tid = threadIdx.x;
    int wid = tid >> 5, lane = tid & 31;
    int g = lane >> 2, tg = lane & 3;
    int q8 = lane >> 3, e8 = lane & 7;
    int warp_m = wid & 3, warp_n = wid >> 2;
    int m0 = blockIdx.y * 256, n0 = blockIdx.x * 128;

    float acc[4][4][4];
    #pragma unroll
    for (int mt = 0; mt < 4; mt++)
        #pragma unroll
        for (int nt = 0; nt < 4; nt++)
            #pragma unroll
            for (int c = 0; c < 4; c++) acc[mt][nt][c] = 0.f;

    const __half* gp[4];
    uint32_t so[4];
    #pragma unroll
    for (int u = 0; u < 4; u++) {
        int f = tid + u * 512;
        if (f < 1024) {
            int row = f >> 2, c = (f & 3) << 3;
            gp[u] = A + (size_t)(m0 + row) * K + c;
            so[u] = (uint32_t)(row * ASTRIDE + c) * 2;
        } else {
            int fb = f - 1024;
            int plane = fb >> 9, fr = fb & 511;
            int row = fr >> 2, c = (fr & 3) << 3;
            gp[u] = (plane ? Bl : Bh) + (size_t)(n0 + row) * K + c;
            so[u] = (uint32_t)(A_PLANE + plane * B_PLANE + row * ASTRIDE + c) * 2;
        }
    }
    const int T = K >> 5;

    auto issue = [&](int t) {
        uint32_t st = sb + (uint32_t)(t & 1) * (F16_STG * 2);
        int k0 = t << 5;
        #pragma unroll
        for (int u = 0; u < 4; u++) cp16(st + so[u], gp[u] + k0);
        cp_commit();
    };

    issue(0);

    uint32_t aoff[4], boff[2];
    #pragma unroll
    for (int mt = 0; mt < 4; mt++)
        aoff[mt] = (uint32_t)((warp_m * 64 + mt * 16 + e8 + (q8 & 1) * 8) * ASTRIDE
                              + (q8 >> 1) * 8);
    #pragma unroll
    for (int p = 0; p < 2; p++)
        boff[p] = (uint32_t)((warp_n * 32 + (2 * p + (q8 >> 1)) * 8 + e8) * ASTRIDE
                             + (q8 & 1) * 8);

    for (int t = 0; t < T; t++) {
        cp_wait0();
        __syncthreads();
        if (t + 1 < T) issue(t + 1);

        uint32_t st = sb + (uint32_t)(t & 1) * (F16_STG * 2);
        #pragma unroll
        for (int ks = 0; ks < 32; ks += 16) {
            uint32_t af[4][4];
            #pragma unroll
            for (int mt = 0; mt < 4; mt++)
                ldm4(st + (aoff[mt] + ks) * 2,
                     af[mt][0], af[mt][1], af[mt][2], af[mt][3]);
            #pragma unroll
            for (int p = 0; p < 2; p++) {
                uint32_t bh0, bh1, bh2, bh3, bl0, bl1, bl2, bl3;
                ldm4(st + (A_PLANE + boff[p] + ks) * 2, bh0, bh1, bh2, bh3);
                ldm4(st + (A_PLANE + B_PLANE + boff[p] + ks) * 2, bl0, bl1, bl2, bl3);
                int ntA = 2 * p, ntB = ntA + 1;
                #pragma unroll
                for (int mt = 0; mt < 4; mt++) {
                    hmma16(acc[mt][ntA], af[mt][0], af[mt][1], af[mt][2], af[mt][3], bh0, bh1);
                    hmma16(acc[mt][ntA], af[mt][0], af[mt][1], af[mt][2], af[mt][3], bl0, bl1);
                    hmma16(acc[mt][ntB], af[mt][0], af[mt][1], af[mt][2], af[mt][3], bh2, bh3);
                    hmma16(acc[mt][ntB], af[mt][0], af[mt][1], af[mt][2], af[mt][3], bl2, bl3);
                }
            }
        }
    }

    #pragma unroll
    for (int mt = 0; mt < 4; mt++) {
        #pragma unroll
        for (int nt = 0; nt < 4; nt++) {
            int row = m0 + warp_m * 64 + mt * 16 + g;
            int col = n0 + warp_n * 32 + nt * 8 + 2 * tg;
            #pragma unroll
            for (int half = 0; half < 2; half++) {
                int r = row + half * 8;
                float v0 = acc[mt][nt][half * 2 + 0];
                float v1 = acc[mt][nt][half * 2 + 1];
                if (bias) { v0 += bias[col]; v1 += bias[col + 1]; }
                if (act) {
                    v0 = v0 / (1.f + __expf(-v0));
                    v1 = v1 / (1.f + __expf(-v1));
                }
                size_t o = (size_t)r * N + col;
                if (outF) {
                    if (res) {
                        float2 rv = *reinterpret_cast<const float2*>(res + o);
                        v0 += rv.x; v1 += rv.y;
                    }
                    *reinterpret_cast<float2*>(outF + o) = make_float2(v0, v1);
                } else if (outL) {
                    uint32_t lo;
                    uint32_t hi = split_pack16(v0, v1, lo);
                    *reinterpret_cast<uint32_t*>(outH + o) = hi;
                    *reinterpret_cast<uint32_t*>(outL + o) = lo;
                } else {
                    *reinterpret_cast<uint32_t*>(out16 + o) = pk16(v0, v1);
                }
            }
        }
    }
}

// ---------------- fp16 2-pass flash attention: 128 q-rows, 256 threads ----------
#define AT_STRIDE 72
#define QPB (128*AT_STRIDE*2)          // single Q plane bytes
#define KPB (64*AT_STRIDE*2)
#define KV_BASE QPB
#define AT_SMEM_BYTES (KV_BASE + 8*KPB + 3*64*4)

__global__ __launch_bounds__(256)
void attn_tc(const __half* __restrict__ qkvh, const __half* __restrict__ qkvl,
             const int* __restrict__ amask, __half* __restrict__ ctx16)
{
    extern __shared__ uint16_t ash[];
    uint32_t sb = s2u(ash);
    float* koff = reinterpret_cast<float*>((char*)ash + KV_BASE + 8 * KPB);

    int tid = threadIdx.x;
    int lane = tid & 31, w = tid >> 5;
    int g = lane >> 2, tg = lane & 3;
    int q8 = lane >> 3, e8 = lane & 7;
    int bh = blockIdx.y;
    int b = bh >> 4, h = bh & 15;
    int qt = gridDim.x - 1 - blockIdx.x;
    int q0 = qt * 128;
    const size_t rowbase = (size_t)b * SS;
    const int hoff = h * 64;
    const int ktmax = 2 * qt + 1;

    // Q cp: 1024 chunks -> 4/thread (hi plane only)
    const __half* qgp[4]; uint32_t qso[4];
    #pragma unroll
    for (int u = 0; u < 4; u++) {
        int f = tid + u * 256;
        int row = f >> 3, c = (f & 7) << 3;
        qgp[u] = qkvh + (rowbase + q0 + row) * QKVD + hoff + c;
        qso[u] = (uint32_t)(row * AT_STRIDE + c) * 2;
    }
    // KV cp: 2048 chunks/buffer -> 8/thread. planes 0=Kh 1=Kl 2=Vh 3=Vl
    const __half* kvgp[8]; uint32_t kvso[8]; int kvrow[8];
    #pragma unroll
    for (int u = 0; u < 8; u++) {
        int f = tid + u * 256;
        int plane = f >> 9, fr = f & 511;
        int row = fr >> 3, c = (fr & 7) << 3;
        const __half* base = (plane == 0) ? qkvh + DD : (plane == 1) ? qkvl + DD
                            : (plane == 2) ? qkvh + 2 * DD : qkvl + 2 * DD;
        kvgp[u] = base + rowbase * QKVD + hoff + c;
        kvrow[u] = row;
        kvso[u] = (uint32_t)KV_BASE + (uint32_t)(plane * (KPB / 2) + row * AT_STRIDE + c) * 2;
    }

    auto issueKV = [&](int kt) {
        uint32_t st = sb + (uint32_t)(kt & 1) * (4 * KPB);
        int k0 = kt * 64;
        #pragma unroll
        for (int u = 0; u < 8; u++)
            cp16(st + kvso[u], kvgp[u] + (size_t)(k0 + kvrow[u]) * QKVD);
        cp_commit();
        if (tid < 64)
            koff[(kt % 3) * 64 + tid] = (amask[b * SS + k0 + tid] == 1) ? 0.f : NEGBIG;
    };

    #pragma unroll
    for (int u = 0; u < 4; u++) cp16(sb + qso[u], qgp[u]);
    cp_commit();
    issueKV(0);
    issueKV(1);
    cp_wait1();
    __syncthreads();

    // Q fragments (single plane)
    uint32_t qf[4][4];
    uint32_t qoffb = (uint32_t)((w * 16 + e8 + (q8 & 1) * 8) * AT_STRIDE + (q8 >> 1) * 8);
    #pragma unroll
    for (int kt = 0; kt < 4; kt++)
        ldm4(sb + (qoffb + 16 * kt) * 2, qf[kt][0], qf[kt][1], qf[kt][2], qf[kt][3]);

    uint32_t kboff[4], vboff[4];
    #pragma unroll
    for (int p = 0; p < 4; p++) {
        kboff[p] = (uint32_t)(((2 * p + (q8 >> 1)) * 8 + e8) * AT_STRIDE + (q8 & 1) * 8);
        vboff[p] = (uint32_t)(((q8 & 1) * 8 + e8) * AT_STRIDE + (2 * p + (q8 >> 1)) * 8);
    }

    float o[8][4];
    #pragma unroll
    for (int nt = 0; nt < 8; nt++)
        #pragma unroll
        for (int c = 0; c < 4; c++) o[nt][c] = 0.f;
    float m0v = NEGBIG, m1v = NEGBIG, l0 = 0.f, l1 = 0.f;
    int r0g = q0 + w * 16 + g, r1g = r0g + 8;

    for (int kt_g = 0; kt_g <= ktmax; kt_g++) {
        int k0 = kt_g * 64;
        if (kt_g == ktmax) cp_wait0(); else cp_wait1();
        __syncthreads();

        uint32_t stK  = sb + KV_BASE + (uint32_t)(kt_g & 1) * (4 * KPB);
        uint32_t stKl = stK + KPB;
        uint32_t stV  = stK + 2 * KPB;
        uint32_t stVl = stK + 3 * KPB;
        const float* kofft = koff + (kt_g % 3) * 64;

        // ---- S = Q K^T (Q single, K hi/lo) ----
        float s[8][4];
        #pragma unroll
        for (int nt = 0; nt < 8; nt++)
            #pragma unroll
            for (int c = 0; c < 4; c++) s[nt][c] = 0.f;
        #pragma unroll
        for (int kt = 0; kt < 4; kt++) {
            #pragma unroll
            for (int p = 0; p < 4; p++) {
                uint32_t bh0, bh1, bh2, bh3, bl0, bl1, bl2, bl3;
                ldm4(stK  + (kboff[p] + 16 * kt) * 2, bh0, bh1, bh2, bh3);
                ldm4(stKl + (kboff[p] + 16 * kt) * 2, bl0, bl1, bl2, bl3);
                int ntA = 2 * p, ntB = ntA + 1;
                hmma16(s[ntA], qf[kt][0], qf[kt][1], qf[kt][2], qf[kt][3], bh0, bh1);
                hmma16(s[ntA], qf[kt][0], qf[kt][1], qf[kt][2], qf[kt][3], bl0, bl1);
                hmma16(s[ntB], qf[kt][0], qf[kt][1], qf[kt][2], qf[kt][3], bh2, bh3);
                hmma16(s[ntB], qf[kt][0], qf[kt][1], qf[kt][2], qf[kt][3], bl2, bl3);
            }
        }

        // ---- scale + mask + row max ----
        float mx0 = NEGBIG, mx1 = NEGBIG;
        #pragma unroll
        for (int nt = 0; nt < 8; nt++) {
            int c0 = k0 + 8 * nt + 2 * tg;
            float kf0 = kofft[8 * nt + 2 * tg], kf1 = kofft[8 * nt + 2 * tg + 1];
            float v0 = s[nt][0] * INV_SCALE + kf0;
            float v1 = s[nt][1] * INV_SCALE + kf1;
            float v2 = s[nt][2] * INV_SCALE + kf0;
            float v3 = s[nt][3] * INV_SCALE + kf1;
            if (c0     > r0g) v0 = NEGBIG;
            if (c0 + 1 > r0g) v1 = NEGBIG;
            if (c0     > r1g) v2 = NEGBIG;
            if (c0 + 1 > r1g) v3 = NEGBIG;
            s[nt][0] = v0; s[nt][1] = v1; s[nt][2] = v2; s[nt][3] = v3;
            mx0 = fmaxf(mx0, fmaxf(v0, v1));
            mx1 = fmaxf(mx1, fmaxf(v2, v3));
        }
        mx0 = fmaxf(mx0, __shfl_xor_sync(0xffffffffu, mx0, 1));
        mx0 = fmaxf(mx0, __shfl_xor_sync(0xffffffffu, mx0, 2));
        mx1 = fmaxf(mx1, __shfl_xor_sync(0xffffffffu, mx1, 1));
        mx1 = fmaxf(mx1, __shfl_xor_sync(0xffffffffu, mx1, 2));

        float mn0 = fmaxf(m0v, mx0), mn1 = fmaxf(m1v, mx1);
        float al0 = __expf(m0v - mn0), al1 = __expf(m1v - mn1);
        m0v = mn0; m1v = mn1;
        l0 *= al0; l1 *= al1;

        #pragma unroll
        for (int nt = 0; nt < 8; nt++) {
            float p0 = __expf(s[nt][0] - m0v);
            float p1 = __expf(s[nt][1] - m0v);
            float p2 = __expf(s[nt][2] - m1v);
            float p3 = __expf(s[nt][3] - m1v);
            s[nt][0] = p0; s[nt][1] = p1; s[nt][2] = p2; s[nt][3] = p3;
            l0 += p0 + p1; l1 += p2 + p3;
        }
        #pragma unroll
        for (int nt = 0; nt < 8; nt++) {
            o[nt][0] *= al0; o[nt][1] *= al0;
            o[nt][2] *= al1; o[nt][3] *= al1;
        }

        // ---- O += P V (P single fp16, V hi/lo) ----
        #pragma unroll
        for (int ktP = 0; ktP < 4; ktP++) {
            int ntA = 2 * ktP, ntB = ntA + 1;
            uint32_t a0 = pk16(s[ntA][0], s[ntA][1]);
            uint32_t a1 = pk16(s[ntA][2], s[ntA][3]);
            uint32_t a2 = pk16(s[ntB][0], s[ntB][1]);
            uint32_t a3 = pk16(s[ntB][2], s[ntB][3]);
            #pragma unroll
            for (int p = 0; p < 4; p++) {
                uint32_t vh0, vh1, vh2, vh3, vl0, vl1, vl2, vl3;
                ldm4t(stV  + (vboff[p] + 16 * ktP * AT_STRIDE) * 2, vh0, vh1, vh2, vh3);
                ldm4t(stVl + (vboff[p] + 16 * ktP * AT_STRIDE) * 2, vl0, vl1, vl2, vl3);
                int n2A = 2 * p, n2B = n2A + 1;
                hmma16(o[n2A], a0, a1, a2, a3, vh0, vh1);
                hmma16(o[n2A], a0, a1, a2, a3, vl0, vl1);
                hmma16(o[n2B], a0, a1, a2, a3, vh2, vh3);
                hmma16(o[n2B], a0, a1, a2, a3, vl2, vl3);
            }
        }

        __syncthreads();
        if (kt_g + 2 <= ktmax) issueKV(kt_g + 2);
    }

    l0 += __shfl_xor_sync(0xffffffffu, l0, 1);
    l0 += __shfl_xor_sync(0xffffffffu, l0, 2);
    l1 += __shfl_xor_sync(0xffffffffu, l1, 1);
    l1 += __shfl_xor_sync(0xffffffffu, l1, 2);
    float inv0 = 1.f / l0, inv1 = 1.f / l1;

    #pragma unroll
    for (int nt = 0; nt < 8; nt++) {
        int col = hoff + 8 * nt + 2 * tg;
        *reinterpret_cast<uint32_t*>(ctx16 + (rowbase + r0g) * DD + col) =
            pk16(o[nt][0] * inv0, o[nt][1] * inv0);
        *reinterpret_cast<uint32_t*>(ctx16 + (rowbase + r1g) * DD + col) =
            pk16(o[nt][2] * inv1, o[nt][3] * inv1);
    }
}

// ---------------- host ---------------------------------------------------------
extern "C" void kernel_launch(void* const* d_in, const int* in_sizes, int n_in,
                              void* d_out, int out_size)
{
    const float* hidden = (const float*)d_in[0];
    const int*   amask  = (const int*)  d_in[1];
    const float* Wq     = (const float*)d_in[2];
    const float* Wk     = (const float*)d_in[3];
    const float* Wv     = (const float*)d_in[4];
    const float* Wo     = (const float*)d_in[5];
    const float* ln1g   = (const float*)d_in[6];
    const float* ln1b   = (const float*)d_in[7];
    const float* W1     = (const float*)d_in[8];
    const float* b1     = (const float*)d_in[9];
    const float* W2     = (const float*)d_in[10];
    const float* b2     = (const float*)d_in[11];
    const float* ln2g   = (const float*)d_in[12];
    const float* ln2b   = (const float*)d_in[13];
    float* out = (float*)d_out;

    __half *x16, *qkvh, *qkvl, *ctx16, *y16, *h16, *wh, *wl;
    float* x2;
    cudaGetSymbolAddress((void**)&x16,  g_x16);
    cudaGetSymbolAddress((void**)&qkvh, g_qkvh);
    cudaGetSymbolAddress((void**)&qkvl, g_qkvl);
    cudaGetSymbolAddress((void**)&ctx16, g_ctx16);
    cudaGetSymbolAddress((void**)&x2,   g_x2);
    cudaGetSymbolAddress((void**)&y16,  g_y16);
    cudaGetSymbolAddress((void**)&h16,  g_h16);
    cudaGetSymbolAddress((void**)&wh,   g_wh);
    cudaGetSymbolAddress((void**)&wl,   g_wl);

    cudaFuncSetAttribute(attn_tc, cudaFuncAttributeMaxDynamicSharedMemorySize,
                         AT_SMEM_BYTES);
    cudaFuncSetAttribute(gemm_f16, cudaFuncAttributeMaxDynamicSharedMemorySize,
                         F16_SMEM);

    const int M = MROWS;

    // weight prep (fp16 hi/lo, [N,K]): QKV@0, Wo@3M1, W1@4M1, W2@8M1
    transsplit16<<<dim3(DD/32, DD/32), 256>>>(Wq, wh,                    wl,                    DD, DD);
    transsplit16<<<dim3(DD/32, DD/32), 256>>>(Wk, wh + M1,               wl + M1,               DD, DD);
    transsplit16<<<dim3(DD/32, DD/32), 256>>>(Wv, wh + 2*(size_t)M1,     wl + 2*(size_t)M1,     DD, DD);
    transsplit16<<<dim3(DD/32, DD/32), 256>>>(Wo, wh + 3*(size_t)M1,     wl + 3*(size_t)M1,     DD, DD);
    transsplit16<<<dim3(FF/32, DD/32), 256>>>(W1, wh + 4*(size_t)M1,     wl + 4*(size_t)M1,     DD, FF);
    transsplit16<<<dim3(DD/32, FF/32), 256>>>(W2, wh + 8*(size_t)M1,     wl + 8*(size_t)M1,     FF, DD);

    // LN1 -> fp16
    ln_f16<<<M, 256>>>(hidden, ln1g, ln1b, x16);
    // fused QKV projection (fp16 2-pass) -> fp16 hi/lo planes
    gemm_f16<<<dim3(QKVD/128, M/256), 512, F16_SMEM>>>(
        x16, wh, wl, nullptr, nullptr, nullptr, nullptr, qkvh, qkvl, M, QKVD, DD, 0);
    // attention (fp16 2-pass) -> ctx fp16
    attn_tc<<<dim3(SS/128, BB*HH), 256, AT_SMEM_BYTES>>>(qkvh, qkvl, amask, ctx16);
    // output projection + residual -> fp32 x2
    gemm_f16<<<dim3(DD/128, M/256), 512, F16_SMEM>>>(
        ctx16, wh + 3*(size_t)M1, wl + 3*(size_t)M1, nullptr, hidden, x2,
        nullptr, nullptr, nullptr, M, DD, DD, 0);
    // LN2 -> fp16
    ln_f16<<<M, 256>>>(x2, ln2g, ln2b, y16);
    // FFN1 (bias + SiLU) -> fp16 h
    gemm_f16<<<dim3(FF/128, M/256), 512, F16_SMEM>>>(
        y16, wh + 4*(size_t)M1, wl + 4*(size_t)M1, b1, nullptr, nullptr, h16,
        nullptr, nullptr, M, FF, DD, 1);
    // FFN2 (bias + residual x2) -> fp32 out
    gemm_f16<<<dim3(DD/128, M/256), 512, F16_SMEM>>>(
        h16, wh + 8*(size_t)M1, wl + 8*(size_t)M1, b2, x2, out, nullptr,
        nullptr, nullptr, M, DD, FF, 0);
}

// round 10
// speedup vs baseline: 5.0419x; 1.5674x over previous
#include <cuda_runtime.h>
#include <cuda_fp16.h>
#include <math.h>
#include <stdint.h>

#define BB 4
#define SS 2048
#define DD 1024
#define FF 4096
#define HH 16
#define QKVD (3*DD)
#define INV_SCALE 0.125f
#define NEGBIG -1e30f
#define MROWS (BB*SS)
#define M1 (DD*DD)

// ---------------- scratch ------------------------------------------------------
__device__ __half g_x16 [MROWS*DD];
__device__ __half g_qkv16[(size_t)MROWS*QKVD];
__device__ __half g_ctx16[MROWS*DD];
__device__ float  g_x2  [MROWS*DD];
__device__ __half g_y16 [MROWS*DD];
__device__ __half g_h16 [(size_t)MROWS*FF];
// weights fp16, [N,K]: QKV@0 (3M1), Wo@3M1 (M1), W1@4M1 (4M1), W2@8M1 (4M1)
__device__ __half g_w16[(size_t)12*M1];

// ---------------- helpers ------------------------------------------------------
__device__ __forceinline__ uint32_t pk16(float a, float b) {
    __half2 h = __floats2half2_rn(a, b);
    return *reinterpret_cast<uint32_t*>(&h);
}
__device__ __forceinline__ void hmma16(float* d, uint32_t a0, uint32_t a1,
                                       uint32_t a2, uint32_t a3,
                                       uint32_t b0, uint32_t b1) {
    asm volatile("mma.sync.aligned.m16n8k16.row.col.f32.f16.f16.f32 "
                 "{%0,%1,%2,%3}, {%4,%5,%6,%7}, {%8,%9}, {%0,%1,%2,%3};"
                 : "+f"(d[0]), "+f"(d[1]), "+f"(d[2]), "+f"(d[3])
                 : "r"(a0), "r"(a1), "r"(a2), "r"(a3), "r"(b0), "r"(b1));
}
__device__ __forceinline__ uint32_t s2u(const void* p) {
    return (uint32_t)__cvta_generic_to_shared(p);
}
__device__ __forceinline__ void cp16(uint32_t dst, const void* src) {
    asm volatile("cp.async.ca.shared.global [%0], [%1], 16;" :: "r"(dst), "l"(src));
}
__device__ __forceinline__ void cp_commit() { asm volatile("cp.async.commit_group;"); }
__device__ __forceinline__ void cp_wait0()  { asm volatile("cp.async.wait_group 0;"); }
__device__ __forceinline__ void cp_wait1()  { asm volatile("cp.async.wait_group 1;"); }
__device__ __forceinline__ void ldm4(uint32_t addr, uint32_t& r0, uint32_t& r1,
                                     uint32_t& r2, uint32_t& r3) {
    asm volatile("ldmatrix.sync.aligned.m8n8.x4.shared.b16 {%0,%1,%2,%3}, [%4];"
                 : "=r"(r0), "=r"(r1), "=r"(r2), "=r"(r3) : "r"(addr));
}
__device__ __forceinline__ void ldm4t(uint32_t addr, uint32_t& r0, uint32_t& r1,
                                      uint32_t& r2, uint32_t& r3) {
    asm volatile("ldmatrix.sync.aligned.m8n8.x4.trans.shared.b16 {%0,%1,%2,%3}, [%4];"
                 : "=r"(r0), "=r"(r1), "=r"(r2), "=r"(r3) : "r"(addr));
}

// ---------------- LayerNorm -> single fp16 -------------------------------------
__global__ __launch_bounds__(256)
void ln_f16(const float* __restrict__ x, const float* __restrict__ g,
            const float* __restrict__ b, __half* __restrict__ out16)
{
    int row = blockIdx.x;
    int tid = threadIdx.x;
    const float* xr = x + (size_t)row * DD;
    float4 v = *reinterpret_cast<const float4*>(xr + tid * 4);
    float s  = v.x + v.y + v.z + v.w;
    float sq = v.x*v.x + v.y*v.y + v.z*v.z + v.w*v.w;
    #pragma unroll
    for (int o = 16; o > 0; o >>= 1) {
        s  += __shfl_xor_sync(0xffffffffu, s,  o);
        sq += __shfl_xor_sync(0xffffffffu, sq, o);
    }
    __shared__ float ws[8], wq[8];
    __shared__ float smean, srstd;
    int wid = tid >> 5, lane = tid & 31;
    if (lane == 0) { ws[wid] = s; wq[wid] = sq; }
    __syncthreads();
    if (tid == 0) {
        float S = 0.f, Q = 0.f;
        #pragma unroll
        for (int i = 0; i < 8; i++) { S += ws[i]; Q += wq[i]; }
        float mean = S * (1.f / DD);
        float var  = fmaxf(Q * (1.f / DD) - mean * mean, 0.f);
        smean = mean;
        srstd = rsqrtf(var + 1e-12f);
    }
    __syncthreads();
    float mean = smean, rstd = srstd;
    float4 gv = *reinterpret_cast<const float4*>(g + tid * 4);
    float4 bv = *reinterpret_cast<const float4*>(b + tid * 4);
    uint2 pk = make_uint2(
        pk16((v.x - mean) * rstd * gv.x + bv.x, (v.y - mean) * rstd * gv.y + bv.y),
        pk16((v.z - mean) * rstd * gv.z + bv.z, (v.w - mean) * rstd * gv.w + bv.w));
    *reinterpret_cast<uint2*>(out16 + (size_t)row * DD + tid * 4) = pk;
}

// ---------------- weight transpose -> fp16 -------------------------------------
__global__ __launch_bounds__(256)
void trans16(const float* __restrict__ W, __half* __restrict__ hT, int K, int N)
{
    __shared__ float tile[32][33];
    int n0 = blockIdx.x * 32, k0 = blockIdx.y * 32;
    int tx = threadIdx.x & 31, ty = threadIdx.x >> 5;
    for (int j = ty; j < 32; j += 8)
        tile[j][tx] = W[(size_t)(k0 + j) * N + n0 + tx];
    __syncthreads();
    for (int j = ty; j < 32; j += 8)
        hT[(size_t)(n0 + j) * K + k0 + tx] = __float2half_rn(tile[tx][j]);
}

// ---------------- single-pass fp16 GEMM: 256x128 tile, 512 threads, 2-stage -----
#define ASTRIDE 40
#define A_PLANE (256*ASTRIDE)
#define B_PLANE (128*ASTRIDE)
#define F16_STG (A_PLANE + B_PLANE)
#define F16_SMEM (2*F16_STG*2)

__global__ __launch_bounds__(512, 1)
void gemm_f16(const __half* __restrict__ A, const __half* __restrict__ B,
              const float* __restrict__ bias, const float* __restrict__ res,
              float* __restrict__ outF, __half* __restrict__ out16,
              int M, int N, int K, int act)
{
    extern __shared__ uint16_t sh[];
    uint32_t sb = s2u(sh);
    int tid = threadIdx.x;
    int wid = tid >> 5, lane = tid & 31;
    int g = lane >> 2, tg = lane & 3;
    int q8 = lane >> 3, e8 = lane & 7;
    int warp_m = wid & 3, warp_n = wid >> 2;
    int m0 = blockIdx.y * 256, n0 = blockIdx.x * 128;

    float acc[4][4][4];
    #pragma unroll
    for (int mt = 0; mt < 4; mt++)
        #pragma unroll
        for (int nt = 0; nt < 4; nt++)
            #pragma unroll
            for (int c = 0; c < 4; c++) acc[mt][nt][c] = 0.f;

    // cp.async: 1536 x 16B per stage -> 3/thread
    const __half* gp[3];
    uint32_t so[3];
    #pragma unroll
    for (int u = 0; u < 3; u++) {
        int f = tid + u * 512;
        if (f < 1024) {
            int row = f >> 2, c = (f & 3) << 3;
            gp[u] = A + (size_t)(m0 + row) * K + c;
            so[u] = (uint32_t)(row * ASTRIDE + c) * 2;
        } else {
            int fb = f - 1024;
            int row = fb >> 2, c = (fb & 3) << 3;
            gp[u] = B + (size_t)(n0 + row) * K + c;
            so[u] = (uint32_t)(A_PLANE + row * ASTRIDE + c) * 2;
        }
    }
    const int T = K >> 5;

    auto issue = [&](int t) {
        uint32_t st = sb + (uint32_t)(t & 1) * (F16_STG * 2);
        int k0 = t << 5;
        #pragma unroll
        for (int u = 0; u < 3; u++) cp16(st + so[u], gp[u] + k0);
        cp_commit();
    };

    issue(0);

    uint32_t aoff[4], boff[2];
    #pragma unroll
    for (int mt = 0; mt < 4; mt++)
        aoff[mt] = (uint32_t)((warp_m * 64 + mt * 16 + e8 + (q8 & 1) * 8) * ASTRIDE
                              + (q8 >> 1) * 8);
    #pragma unroll
    for (int p = 0; p < 2; p++)
        boff[p] = (uint32_t)((warp_n * 32 + (2 * p + (q8 >> 1)) * 8 + e8) * ASTRIDE
                             + (q8 & 1) * 8);

    for (int t = 0; t < T; t++) {
        cp_wait0();
        __syncthreads();
        if (t + 1 < T) issue(t + 1);

        uint32_t st = sb + (uint32_t)(t & 1) * (F16_STG * 2);
        #pragma unroll
        for (int ks = 0; ks < 32; ks += 16) {
            uint32_t af[4][4];
            #pragma unroll
            for (int mt = 0; mt < 4; mt++)
                ldm4(st + (aoff[mt] + ks) * 2,
                     af[mt][0], af[mt][1], af[mt][2], af[mt][3]);
            #pragma unroll
            for (int p = 0; p < 2; p++) {
                uint32_t b0, b1, b2, b3;
                ldm4(st + (A_PLANE + boff[p] + ks) * 2, b0, b1, b2, b3);
                int ntA = 2 * p, ntB = ntA + 1;
                #pragma unroll
                for (int mt = 0; mt < 4; mt++) {
                    hmma16(acc[mt][ntA], af[mt][0], af[mt][1], af[mt][2], af[mt][3], b0, b1);
                    hmma16(acc[mt][ntB], af[mt][0], af[mt][1], af[mt][2], af[mt][3], b2, b3);
                }
            }
        }
    }

    #pragma unroll
    for (int mt = 0; mt < 4; mt++) {
        #pragma unroll
        for (int nt = 0; nt < 4; nt++) {
            int row = m0 + warp_m * 64 + mt * 16 + g;
            int col = n0 + warp_n * 32 + nt * 8 + 2 * tg;
            #pragma unroll
            for (int half = 0; half < 2; half++) {
                int r = row + half * 8;
                float v0 = acc[mt][nt][half * 2 + 0];
                float v1 = acc[mt][nt][half * 2 + 1];
                if (bias) { v0 += bias[col]; v1 += bias[col + 1]; }
                if (act) {
                    v0 = v0 / (1.f + __expf(-v0));
                    v1 = v1 / (1.f + __expf(-v1));
                }
                size_t o = (size_t)r * N + col;
                if (outF) {
                    if (res) {
                        float2 rv = *reinterpret_cast<const float2*>(res + o);
                        v0 += rv.x; v1 += rv.y;
                    }
                    *reinterpret_cast<float2*>(outF + o) = make_float2(v0, v1);
                } else {
                    *reinterpret_cast<uint32_t*>(out16 + o) = pk16(v0, v1);
                }
            }
        }
    }
}

// ---------------- fp16 flash attention: 128 q-rows, 256 threads -----------------
#define AT_STRIDE 72
#define QPB (128*AT_STRIDE*2)          // Q plane bytes
#define KPB (64*AT_STRIDE*2)           // K or V plane bytes
#define KV_BASE QPB
#define AT_SMEM_BYTES (KV_BASE + 4*KPB + 3*64*4)

__global__ __launch_bounds__(256)
void attn_tc(const __half* __restrict__ qkv, const int* __restrict__ amask,
             __half* __restrict__ ctx16)
{
    extern __shared__ uint16_t ash[];
    uint32_t sb = s2u(ash);
    float* koff = reinterpret_cast<float*>((char*)ash + KV_BASE + 4 * KPB);

    int tid = threadIdx.x;
    int lane = tid & 31, w = tid >> 5;
    int g = lane >> 2, tg = lane & 3;
    int q8 = lane >> 3, e8 = lane & 7;
    int bh = blockIdx.y;
    int b = bh >> 4, h = bh & 15;
    int qt = gridDim.x - 1 - blockIdx.x;
    int q0 = qt * 128;
    const size_t rowbase = (size_t)b * SS;
    const int hoff = h * 64;
    const int ktmax = 2 * qt + 1;

    // Q cp: 1024 chunks -> 4/thread
    const __half* qgp[4]; uint32_t qso[4];
    #pragma unroll
    for (int u = 0; u < 4; u++) {
        int f = tid + u * 256;
        int row = f >> 3, c = (f & 7) << 3;
        qgp[u] = qkv + (rowbase + q0 + row) * QKVD + hoff + c;
        qso[u] = (uint32_t)(row * AT_STRIDE + c) * 2;
    }
    // KV cp: 1024 chunks/buffer -> 4/thread. planes: 0=K, 1=V
    const __half* kvgp[4]; uint32_t kvso[4]; int kvrow[4];
    #pragma unroll
    for (int u = 0; u < 4; u++) {
        int f = tid + u * 256;
        int plane = f >> 9, fr = f & 511;
        int row = fr >> 3, c = (fr & 7) << 3;
        kvgp[u] = qkv + (plane ? 2 * DD : DD) + rowbase * QKVD + hoff + c;
        kvrow[u] = row;
        kvso[u] = (uint32_t)KV_BASE + (uint32_t)(plane * (KPB / 2) + row * AT_STRIDE + c) * 2;
    }

    auto issueKV = [&](int kt) {
        uint32_t st = sb + (uint32_t)(kt & 1) * (2 * KPB);
        int k0 = kt * 64;
        #pragma unroll
        for (int u = 0; u < 4; u++)
            cp16(st + kvso[u], kvgp[u] + (size_t)(k0 + kvrow[u]) * QKVD);
        cp_commit();
        if (tid < 64)
            koff[(kt % 3) * 64 + tid] = (amask[b * SS + k0 + tid] == 1) ? 0.f : NEGBIG;
    };

    #pragma unroll
    for (int u = 0; u < 4; u++) cp16(sb + qso[u], qgp[u]);
    cp_commit();
    issueKV(0);
    issueKV(1);
    cp_wait1();
    __syncthreads();

    // Q fragments
    uint32_t qf[4][4];
    uint32_t qoffb = (uint32_t)((w * 16 + e8 + (q8 & 1) * 8) * AT_STRIDE + (q8 >> 1) * 8);
    #pragma unroll
    for (int kt = 0; kt < 4; kt++)
        ldm4(sb + (qoffb + 16 * kt) * 2, qf[kt][0], qf[kt][1], qf[kt][2], qf[kt][3]);

    uint32_t kboff[4], vboff[4];
    #pragma unroll
    for (int p = 0; p < 4; p++) {
        kboff[p] = (uint32_t)(((2 * p + (q8 >> 1)) * 8 + e8) * AT_STRIDE + (q8 & 1) * 8);
        vboff[p] = (uint32_t)(((q8 & 1) * 8 + e8) * AT_STRIDE + (2 * p + (q8 >> 1)) * 8);
    }

    float o[8][4];
    #pragma unroll
    for (int nt = 0; nt < 8; nt++)
        #pragma unroll
        for (int c = 0; c < 4; c++) o[nt][c] = 0.f;
    float m0v = NEGBIG, m1v = NEGBIG, l0 = 0.f, l1 = 0.f;
    int r0g = q0 + w * 16 + g, r1g = r0g + 8;

    for (int kt_g = 0; kt_g <= ktmax; kt_g++) {
        int k0 = kt_g * 64;
        if (kt_g == ktmax) cp_wait0(); else cp_wait1();
        __syncthreads();

        uint32_t stK = sb + KV_BASE + (uint32_t)(kt_g & 1) * (2 * KPB);
        uint32_t stV = stK + KPB;
        const float* kofft = koff + (kt_g % 3) * 64;

        // ---- S = Q K^T ----
        float s[8][4];
        #pragma unroll
        for (int nt = 0; nt < 8; nt++)
            #pragma unroll
            for (int c = 0; c < 4; c++) s[nt][c] = 0.f;
        #pragma unroll
        for (int kt = 0; kt < 4; kt++) {
            #pragma unroll
            for (int p = 0; p < 4; p++) {
                uint32_t b0, b1, b2, b3;
                ldm4(stK + (kboff[p] + 16 * kt) * 2, b0, b1, b2, b3);
                int ntA = 2 * p, ntB = ntA + 1;
                hmma16(s[ntA], qf[kt][0], qf[kt][1], qf[kt][2], qf[kt][3], b0, b1);
                hmma16(s[ntB], qf[kt][0], qf[kt][1], qf[kt][2], qf[kt][3], b2, b3);
            }
        }

        // ---- scale + mask + row max ----
        float mx0 = NEGBIG, mx1 = NEGBIG;
        #pragma unroll
        for (int nt = 0; nt < 8; nt++) {
            int c0 = k0 + 8 * nt + 2 * tg;
            float kf0 = kofft[8 * nt + 2 * tg], kf1 = kofft[8 * nt + 2 * tg + 1];
            float v0 = s[nt][0] * INV_SCALE + kf0;
            float v1 = s[nt][1] * INV_SCALE + kf1;
            float v2 = s[nt][2] * INV_SCALE + kf0;
            float v3 = s[nt][3] * INV_SCALE + kf1;
            if (c0     > r0g) v0 = NEGBIG;
            if (c0 + 1 > r0g) v1 = NEGBIG;
            if (c0     > r1g) v2 = NEGBIG;
            if (c0 + 1 > r1g) v3 = NEGBIG;
            s[nt][0] = v0; s[nt][1] = v1; s[nt][2] = v2; s[nt][3] = v3;
            mx0 = fmaxf(mx0, fmaxf(v0, v1));
            mx1 = fmaxf(mx1, fmaxf(v2, v3));
        }
        mx0 = fmaxf(mx0, __shfl_xor_sync(0xffffffffu, mx0, 1));
        mx0 = fmaxf(mx0, __shfl_xor_sync(0xffffffffu, mx0, 2));
        mx1 = fmaxf(mx1, __shfl_xor_sync(0xffffffffu, mx1, 1));
        mx1 = fmaxf(mx1, __shfl_xor_sync(0xffffffffu, mx1, 2));

        float mn0 = fmaxf(m0v, mx0), mn1 = fmaxf(m1v, mx1);
        float al0 = __expf(m0v - mn0), al1 = __expf(m1v - mn1);
        m0v = mn0; m1v = mn1;
        l0 *= al0; l1 *= al1;

        #pragma unroll
        for (int nt = 0; nt < 8; nt++) {
            float p0 = __expf(s[nt][0] - m0v);
            float p1 = __expf(s[nt][1] - m0v);
            float p2 = __expf(s[nt][2] - m1v);
            float p3 = __expf(s[nt][3] - m1v);
            s[nt][0] = p0; s[nt][1] = p1; s[nt][2] = p2; s[nt][3] = p3;
            l0 += p0 + p1; l1 += p2 + p3;
        }
        #pragma unroll
        for (int nt = 0; nt < 8; nt++) {
            o[nt][0] *= al0; o[nt][1] *= al0;
            o[nt][2] *= al1; o[nt][3] *= al1;
        }

        // ---- O += P V ----
        #pragma unroll
        for (int ktP = 0; ktP < 4; ktP++) {
            int ntA = 2 * ktP, ntB = ntA + 1;
            uint32_t a0 = pk16(s[ntA][0], s[ntA][1]);
            uint32_t a1 = pk16(s[ntA][2], s[ntA][3]);
            uint32_t a2 = pk16(s[ntB][0], s[ntB][1]);
            uint32_t a3 = pk16(s[ntB][2], s[ntB][3]);
            #pragma unroll
            for (int p = 0; p < 4; p++) {
                uint32_t v0, v1, v2, v3;
                ldm4t(stV + (vboff[p] + 16 * ktP * AT_STRIDE) * 2, v0, v1, v2, v3);
                int n2A = 2 * p, n2B = n2A + 1;
                hmma16(o[n2A], a0, a1, a2, a3, v0, v1);
                hmma16(o[n2B], a0, a1, a2, a3, v2, v3);
            }
        }

        __syncthreads();
        if (kt_g + 2 <= ktmax) issueKV(kt_g + 2);
    }

    l0 += __shfl_xor_sync(0xffffffffu, l0, 1);
    l0 += __shfl_xor_sync(0xffffffffu, l0, 2);
    l1 += __shfl_xor_sync(0xffffffffu, l1, 1);
    l1 += __shfl_xor_sync(0xffffffffu, l1, 2);
    float inv0 = 1.f / l0, inv1 = 1.f / l1;

    #pragma unroll
    for (int nt = 0; nt < 8; nt++) {
        int col = hoff + 8 * nt + 2 * tg;
        *reinterpret_cast<uint32_t*>(ctx16 + (rowbase + r0g) * DD + col) =
            pk16(o[nt][0] * inv0, o[nt][1] * inv0);
        *reinterpret_cast<uint32_t*>(ctx16 + (rowbase + r1g) * DD + col) =
            pk16(o[nt][2] * inv1, o[nt][3] * inv1);
    }
}

// ---------------- host ---------------------------------------------------------
extern "C" void kernel_launch(void* const* d_in, const int* in_sizes, int n_in,
                              void* d_out, int out_size)
{
    const float* hidden = (const float*)d_in[0];
    const int*   amask  = (const int*)  d_in[1];
    const float* Wq     = (const float*)d_in[2];
    const float* Wk     = (const float*)d_in[3];
    const float* Wv     = (const float*)d_in[4];
    const float* Wo     = (const float*)d_in[5];
    const float* ln1g   = (const float*)d_in[6];
    const float* ln1b   = (const float*)d_in[7];
    const float* W1     = (const float*)d_in[8];
    const float* b1     = (const float*)d_in[9];
    const float* W2     = (const float*)d_in[10];
    const float* b2     = (const float*)d_in[11];
    const float* ln2g   = (const float*)d_in[12];
    const float* ln2b   = (const float*)d_in[13];
    float* out = (float*)d_out;

    __half *x16, *qkv16, *ctx16, *y16, *h16, *w16;
    float* x2;
    cudaGetSymbolAddress((void**)&x16,   g_x16);
    cudaGetSymbolAddress((void**)&qkv16, g_qkv16);
    cudaGetSymbolAddress((void**)&ctx16, g_ctx16);
    cudaGetSymbolAddress((void**)&x2,    g_x2);
    cudaGetSymbolAddress((void**)&y16,   g_y16);
    cudaGetSymbolAddress((void**)&h16,   g_h16);
    cudaGetSymbolAddress((void**)&w16,   g_w16);

    cudaFuncSetAttribute(attn_tc, cudaFuncAttributeMaxDynamicSharedMemorySize,
                         AT_SMEM_BYTES);
    cudaFuncSetAttribute(gemm_f16, cudaFuncAttributeMaxDynamicSharedMemorySize,
                         F16_SMEM);

    const int M = MROWS;

    // weight prep (fp16, [N,K]): QKV@0, Wo@3M1, W1@4M1, W2@8M1
    trans16<<<dim3(DD/32, DD/32), 256>>>(Wq, w16,                  DD, DD);
    trans16<<<dim3(DD/32, DD/32), 256>>>(Wk, w16 + M1,             DD, DD);
    trans16<<<dim3(DD/32, DD/32), 256>>>(Wv, w16 + 2*(size_t)M1,   DD, DD);
    trans16<<<dim3(DD/32, DD/32), 256>>>(Wo, w16 + 3*(size_t)M1,   DD, DD);
    trans16<<<dim3(FF/32, DD/32), 256>>>(W1, w16 + 4*(size_t)M1,   DD, FF);
    trans16<<<dim3(DD/32, FF/32), 256>>>(W2, w16 + 8*(size_t)M1,   FF, DD);

    // LN1 -> fp16
    ln_f16<<<M, 256>>>(hidden, ln1g, ln1b, x16);
    // fused QKV projection -> fp16
    gemm_f16<<<dim3(QKVD/128, M/256), 512, F16_SMEM>>>(
        x16, w16, nullptr, nullptr, nullptr, qkv16, M, QKVD, DD, 0);
    // attention -> ctx fp16
    attn_tc<<<dim3(SS/128, BB*HH), 256, AT_SMEM_BYTES>>>(qkv16, amask, ctx16);
    // output projection + residual -> fp32 x2
    gemm_f16<<<dim3(DD/128, M/256), 512, F16_SMEM>>>(
        ctx16, w16 + 3*(size_t)M1, nullptr, hidden, x2, nullptr, M, DD, DD, 0);
    // LN2 -> fp16
    ln_f16<<<M, 256>>>(x2, ln2g, ln2b, y16);
    // FFN1 (bias + SiLU) -> fp16 h
    gemm_f16<<<dim3(FF/128, M/256), 512, F16_SMEM>>>(
        y16, w16 + 4*(size_t)M1, b1, nullptr, nullptr, h16, M, FF, DD, 1);
    // FFN2 (bias + residual x2) -> fp32 out
    gemm_f16<<<dim3(DD/128, M/256), 512, F16_SMEM>>>(
        h16, w16 + 8*(size_t)M1, b2, x2, out, nullptr, M, DD, FF, 0);
}

// round 11
// speedup vs baseline: 5.1165x; 1.0148x over previous
#include <cuda_runtime.h>
#include <cuda_fp16.h>
#include <math.h>
#include <stdint.h>

#define BB 4
#define SS 2048
#define DD 1024
#define FF 4096
#define HH 16
#define QKVD (3*DD)
#define NEGBIG -1e30f
#define MROWS (BB*SS)
#define M1 (DD*DD)
// 0.125 * log2(e) folded into Q
#define QSCALE 0.1803368801111204f

// ---------------- scratch ------------------------------------------------------
__device__ __half g_x16 [MROWS*DD];
__device__ __half g_qkv16[(size_t)MROWS*QKVD];
__device__ __half g_ctx16[MROWS*DD];
__device__ float  g_x2  [MROWS*DD];
__device__ __half g_y16 [MROWS*DD];
__device__ __half g_h16 [(size_t)MROWS*FF];
__device__ __half g_w16[(size_t)12*M1];

// ---------------- helpers ------------------------------------------------------
__device__ __forceinline__ uint32_t pk16(float a, float b) {
    __half2 h = __floats2half2_rn(a, b);
    return *reinterpret_cast<uint32_t*>(&h);
}
__device__ __forceinline__ float ex2f(float x) {
    float r;
    asm("ex2.approx.f32 %0, %1;" : "=f"(r) : "f"(x));
    return r;
}
__device__ __forceinline__ void hmma16(float* d, uint32_t a0, uint32_t a1,
                                       uint32_t a2, uint32_t a3,
                                       uint32_t b0, uint32_t b1) {
    asm volatile("mma.sync.aligned.m16n8k16.row.col.f32.f16.f16.f32 "
                 "{%0,%1,%2,%3}, {%4,%5,%6,%7}, {%8,%9}, {%0,%1,%2,%3};"
                 : "+f"(d[0]), "+f"(d[1]), "+f"(d[2]), "+f"(d[3])
                 : "r"(a0), "r"(a1), "r"(a2), "r"(a3), "r"(b0), "r"(b1));
}
__device__ __forceinline__ uint32_t s2u(const void* p) {
    return (uint32_t)__cvta_generic_to_shared(p);
}
__device__ __forceinline__ void cp16(uint32_t dst, const void* src) {
    asm volatile("cp.async.ca.shared.global [%0], [%1], 16;" :: "r"(dst), "l"(src));
}
__device__ __forceinline__ void cp_commit() { asm volatile("cp.async.commit_group;"); }
__device__ __forceinline__ void cp_wait0()  { asm volatile("cp.async.wait_group 0;"); }
__device__ __forceinline__ void cp_wait1()  { asm volatile("cp.async.wait_group 1;"); }
__device__ __forceinline__ void ldm4(uint32_t addr, uint32_t& r0, uint32_t& r1,
                                     uint32_t& r2, uint32_t& r3) {
    asm volatile("ldmatrix.sync.aligned.m8n8.x4.shared.b16 {%0,%1,%2,%3}, [%4];"
                 : "=r"(r0), "=r"(r1), "=r"(r2), "=r"(r3) : "r"(addr));
}
__device__ __forceinline__ void ldm4t(uint32_t addr, uint32_t& r0, uint32_t& r1,
                                      uint32_t& r2, uint32_t& r3) {
    asm volatile("ldmatrix.sync.aligned.m8n8.x4.trans.shared.b16 {%0,%1,%2,%3}, [%4];"
                 : "=r"(r0), "=r"(r1), "=r"(r2), "=r"(r3) : "r"(addr));
}

// ---------------- LayerNorm -> single fp16 -------------------------------------
__global__ __launch_bounds__(256)
void ln_f16(const float* __restrict__ x, const float* __restrict__ g,
            const float* __restrict__ b, __half* __restrict__ out16)
{
    int row = blockIdx.x;
    int tid = threadIdx.x;
    const float* xr = x + (size_t)row * DD;
    float4 v = *reinterpret_cast<const float4*>(xr + tid * 4);
    float s  = v.x + v.y + v.z + v.w;
    float sq = v.x*v.x + v.y*v.y + v.z*v.z + v.w*v.w;
    #pragma unroll
    for (int o = 16; o > 0; o >>= 1) {
        s  += __shfl_xor_sync(0xffffffffu, s,  o);
        sq += __shfl_xor_sync(0xffffffffu, sq, o);
    }
    __shared__ float ws[8], wq[8];
    __shared__ float smean, srstd;
    int wid = tid >> 5, lane = tid & 31;
    if (lane == 0) { ws[wid] = s; wq[wid] = sq; }
    __syncthreads();
    if (tid == 0) {
        float S = 0.f, Q = 0.f;
        #pragma unroll
        for (int i = 0; i < 8; i++) { S += ws[i]; Q += wq[i]; }
        float mean = S * (1.f / DD);
        float var  = fmaxf(Q * (1.f / DD) - mean * mean, 0.f);
        smean = mean;
        srstd = rsqrtf(var + 1e-12f);
    }
    __syncthreads();
    float mean = smean, rstd = srstd;
    float4 gv = *reinterpret_cast<const float4*>(g + tid * 4);
    float4 bv = *reinterpret_cast<const float4*>(b + tid * 4);
    uint2 pk = make_uint2(
        pk16((v.x - mean) * rstd * gv.x + bv.x, (v.y - mean) * rstd * gv.y + bv.y),
        pk16((v.z - mean) * rstd * gv.z + bv.z, (v.w - mean) * rstd * gv.w + bv.w));
    *reinterpret_cast<uint2*>(out16 + (size_t)row * DD + tid * 4) = pk;
}

// ---------------- weight transpose -> fp16 -------------------------------------
__global__ __launch_bounds__(256)
void trans16(const float* __restrict__ W, __half* __restrict__ hT, int K, int N)
{
    __shared__ float tile[32][33];
    int n0 = blockIdx.x * 32, k0 = blockIdx.y * 32;
    int tx = threadIdx.x & 31, ty = threadIdx.x >> 5;
    for (int j = ty; j < 32; j += 8)
        tile[j][tx] = W[(size_t)(k0 + j) * N + n0 + tx];
    __syncthreads();
    for (int j = ty; j < 32; j += 8)
        hT[(size_t)(n0 + j) * K + k0 + tx] = __float2half_rn(tile[tx][j]);
}

// ---------------- single-pass fp16 GEMM: 256x128 tile, 512 threads, 2-stage -----
#define ASTRIDE 40
#define A_PLANE (256*ASTRIDE)
#define B_PLANE (128*ASTRIDE)
#define F16_STG (A_PLANE + B_PLANE)
#define F16_SMEM (2*F16_STG*2)

__global__ __launch_bounds__(512, 1)
void gemm_f16(const __half* __restrict__ A, const __half* __restrict__ B,
              const float* __restrict__ bias, const float* __restrict__ res,
              float* __restrict__ outF, __half* __restrict__ out16,
              int M, int N, int K, int act, int qcols)
{
    extern __shared__ uint16_t sh[];
    uint32_t sb = s2u(sh);
    int tid = threadIdx.x;
    int wid = tid >> 5, lane = tid & 31;
    int g = lane >> 2, tg = lane & 3;
    int q8 = lane >> 3, e8 = lane & 7;
    int warp_m = wid & 3, warp_n = wid >> 2;
    int m0 = blockIdx.y * 256, n0 = blockIdx.x * 128;
    // whole CTA tile is either inside or outside the q-column range
    float cscale = (n0 < qcols) ? QSCALE : 1.f;

    float acc[4][4][4];
    #pragma unroll
    for (int mt = 0; mt < 4; mt++)
        #pragma unroll
        for (int nt = 0; nt < 4; nt++)
            #pragma unroll
            for (int c = 0; c < 4; c++) acc[mt][nt][c] = 0.f;

    const __half* gp[3];
    uint32_t so[3];
    #pragma unroll
    for (int u = 0; u < 3; u++) {
        int f = tid + u * 512;
        if (f < 1024) {
            int row = f >> 2, c = (f & 3) << 3;
            gp[u] = A + (size_t)(m0 + row) * K + c;
            so[u] = (uint32_t)(row * ASTRIDE + c) * 2;
        } else {
            int fb = f - 1024;
            int row = fb >> 2, c = (fb & 3) << 3;
            gp[u] = B + (size_t)(n0 + row) * K + c;
            so[u] = (uint32_t)(A_PLANE + row * ASTRIDE + c) * 2;
        }
    }
    const int T = K >> 5;

    auto issue = [&](int t) {
        uint32_t st = sb + (uint32_t)(t & 1) * (F16_STG * 2);
        int k0 = t << 5;
        #pragma unroll
        for (int u = 0; u < 3; u++) cp16(st + so[u], gp[u] + k0);
        cp_commit();
    };

    issue(0);

    uint32_t aoff[4], boff[2];
    #pragma unroll
    for (int mt = 0; mt < 4; mt++)
        aoff[mt] = (uint32_t)((warp_m * 64 + mt * 16 + e8 + (q8 & 1) * 8) * ASTRIDE
                              + (q8 >> 1) * 8);
    #pragma unroll
    for (int p = 0; p < 2; p++)
        boff[p] = (uint32_t)((warp_n * 32 + (2 * p + (q8 >> 1)) * 8 + e8) * ASTRIDE
                             + (q8 & 1) * 8);

    for (int t = 0; t < T; t++) {
        cp_wait0();
        __syncthreads();
        if (t + 1 < T) issue(t + 1);

        uint32_t st = sb + (uint32_t)(t & 1) * (F16_STG * 2);
        #pragma unroll
        for (int ks = 0; ks < 32; ks += 16) {
            uint32_t af[4][4];
            #pragma unroll
            for (int mt = 0; mt < 4; mt++)
                ldm4(st + (aoff[mt] + ks) * 2,
                     af[mt][0], af[mt][1], af[mt][2], af[mt][3]);
            #pragma unroll
            for (int p = 0; p < 2; p++) {
                uint32_t b0, b1, b2, b3;
                ldm4(st + (A_PLANE + boff[p] + ks) * 2, b0, b1, b2, b3);
                int ntA = 2 * p, ntB = ntA + 1;
                #pragma unroll
                for (int mt = 0; mt < 4; mt++) {
                    hmma16(acc[mt][ntA], af[mt][0], af[mt][1], af[mt][2], af[mt][3], b0, b1);
                    hmma16(acc[mt][ntB], af[mt][0], af[mt][1], af[mt][2], af[mt][3], b2, b3);
                }
            }
        }
    }

    #pragma unroll
    for (int mt = 0; mt < 4; mt++) {
        #pragma unroll
        for (int nt = 0; nt < 4; nt++) {
            int row = m0 + warp_m * 64 + mt * 16 + g;
            int col = n0 + warp_n * 32 + nt * 8 + 2 * tg;
            #pragma unroll
            for (int half = 0; half < 2; half++) {
                int r = row + half * 8;
                float v0 = acc[mt][nt][half * 2 + 0];
                float v1 = acc[mt][nt][half * 2 + 1];
                if (bias) { v0 += bias[col]; v1 += bias[col + 1]; }
                if (act) {
                    v0 = v0 / (1.f + __expf(-v0));
                    v1 = v1 / (1.f + __expf(-v1));
                }
                v0 *= cscale; v1 *= cscale;
                size_t o = (size_t)r * N + col;
                if (outF) {
                    if (res) {
                        float2 rv = *reinterpret_cast<const float2*>(res + o);
                        v0 += rv.x; v1 += rv.y;
                    }
                    *reinterpret_cast<float2*>(outF + o) = make_float2(v0, v1);
                } else {
                    *reinterpret_cast<uint32_t*>(out16 + o) = pk16(v0, v1);
                }
            }
        }
    }
}

// ---------------- fp16 flash attention: 128 q-rows, 256 threads, 2 CTA/SM -------
#define AT_STRIDE 72
#define QPB (128*AT_STRIDE*2)
#define KPB (64*AT_STRIDE*2)
#define KV_BASE QPB
#define AT_SMEM_BYTES (KV_BASE + 4*KPB + 3*64*4)

__global__ __launch_bounds__(256, 2)
void attn_tc(const __half* __restrict__ qkv, const int* __restrict__ amask,
             __half* __restrict__ ctx16)
{
    extern __shared__ uint16_t ash[];
    uint32_t sb = s2u(ash);
    float* koff = reinterpret_cast<float*>((char*)ash + KV_BASE + 4 * KPB);

    int tid = threadIdx.x;
    int lane = tid & 31, w = tid >> 5;
    int g = lane >> 2, tg = lane & 3;
    int q8 = lane >> 3, e8 = lane & 7;
    int bh = blockIdx.y;
    int b = bh >> 4, h = bh & 15;
    int qt = gridDim.x - 1 - blockIdx.x;
    int q0 = qt * 128;
    const size_t rowbase = (size_t)b * SS;
    const int hoff = h * 64;
    const int ktmax = 2 * qt + 1;

    const __half* qgp[4]; uint32_t qso[4];
    #pragma unroll
    for (int u = 0; u < 4; u++) {
        int f = tid + u * 256;
        int row = f >> 3, c = (f & 7) << 3;
        qgp[u] = qkv + (rowbase + q0 + row) * QKVD + hoff + c;
        qso[u] = (uint32_t)(row * AT_STRIDE + c) * 2;
    }
    const __half* kvgp[4]; uint32_t kvso[4]; int kvrow[4];
    #pragma unroll
    for (int u = 0; u < 4; u++) {
        int f = tid + u * 256;
        int plane = f >> 9, fr = f & 511;
        int row = fr >> 3, c = (fr & 7) << 3;
        kvgp[u] = qkv + (plane ? 2 * DD : DD) + rowbase * QKVD + hoff + c;
        kvrow[u] = row;
        kvso[u] = (uint32_t)KV_BASE + (uint32_t)(plane * (KPB / 2) + row * AT_STRIDE + c) * 2;
    }

    auto issueKV = [&](int kt) {
        uint32_t st = sb + (uint32_t)(kt & 1) * (2 * KPB);
        int k0 = kt * 64;
        #pragma unroll
        for (int u = 0; u < 4; u++)
            cp16(st + kvso[u], kvgp[u] + (size_t)(k0 + kvrow[u]) * QKVD);
        cp_commit();
        if (tid < 64)
            koff[(kt % 3) * 64 + tid] = (amask[b * SS + k0 + tid] == 1) ? 0.f : NEGBIG;
    };

    #pragma unroll
    for (int u = 0; u < 4; u++) cp16(sb + qso[u], qgp[u]);
    cp_commit();
    issueKV(0);
    issueKV(1);
    cp_wait1();
    __syncthreads();

    uint32_t qf[4][4];
    uint32_t qoffb = (uint32_t)((w * 16 + e8 + (q8 & 1) * 8) * AT_STRIDE + (q8 >> 1) * 8);
    #pragma unroll
    for (int kt = 0; kt < 4; kt++)
        ldm4(sb + (qoffb + 16 * kt) * 2, qf[kt][0], qf[kt][1], qf[kt][2], qf[kt][3]);

    uint32_t kboff[4], vboff[4];
    #pragma unroll
    for (int p = 0; p < 4; p++) {
        kboff[p] = (uint32_t)(((2 * p + (q8 >> 1)) * 8 + e8) * AT_STRIDE + (q8 & 1) * 8);
        vboff[p] = (uint32_t)(((q8 & 1) * 8 + e8) * AT_STRIDE + (2 * p + (q8 >> 1)) * 8);
    }

    float o[8][4];
    #pragma unroll
    for (int nt = 0; nt < 8; nt++)
        #pragma unroll
        for (int c = 0; c < 4; c++) o[nt][c] = 0.f;
    float m0v = NEGBIG, m1v = NEGBIG, l0 = 0.f, l1 = 0.f;
    int r0g = q0 + w * 16 + g, r1g = r0g + 8;

    for (int kt_g = 0; kt_g <= ktmax; kt_g++) {
        int k0 = kt_g * 64;
        if (kt_g == ktmax) cp_wait0(); else cp_wait1();
        __syncthreads();

        uint32_t stK = sb + KV_BASE + (uint32_t)(kt_g & 1) * (2 * KPB);
        uint32_t stV = stK + KPB;
        const float* kofft = koff + (kt_g % 3) * 64;

        // ---- S = Q K^T (Q pre-scaled by 0.125*log2e) ----
        float s[8][4];
        #pragma unroll
        for (int nt = 0; nt < 8; nt++)
            #pragma unroll
            for (int c = 0; c < 4; c++) s[nt][c] = 0.f;
        #pragma unroll
        for (int kt = 0; kt < 4; kt++) {
            #pragma unroll
            for (int p = 0; p < 4; p++) {
                uint32_t b0, b1, b2, b3;
                ldm4(stK + (kboff[p] + 16 * kt) * 2, b0, b1, b2, b3);
                int ntA = 2 * p, ntB = ntA + 1;
                hmma16(s[ntA], qf[kt][0], qf[kt][1], qf[kt][2], qf[kt][3], b0, b1);
                hmma16(s[ntB], qf[kt][0], qf[kt][1], qf[kt][2], qf[kt][3], b2, b3);
            }
        }

        // ---- pad mask (+ causal only on possible-diagonal tiles) + row max ----
        float mx0 = NEGBIG, mx1 = NEGBIG;
        if (kt_g >= 2 * qt) {
            #pragma unroll
            for (int nt = 0; nt < 8; nt++) {
                int c0 = k0 + 8 * nt + 2 * tg;
                float kf0 = kofft[8 * nt + 2 * tg], kf1 = kofft[8 * nt + 2 * tg + 1];
                float v0 = s[nt][0] + kf0;
                float v1 = s[nt][1] + kf1;
                float v2 = s[nt][2] + kf0;
                float v3 = s[nt][3] + kf1;
                if (c0     > r0g) v0 = NEGBIG;
                if (c0 + 1 > r0g) v1 = NEGBIG;
                if (c0     > r1g) v2 = NEGBIG;
                if (c0 + 1 > r1g) v3 = NEGBIG;
                s[nt][0] = v0; s[nt][1] = v1; s[nt][2] = v2; s[nt][3] = v3;
                mx0 = fmaxf(mx0, fmaxf(v0, v1));
                mx1 = fmaxf(mx1, fmaxf(v2, v3));
            }
        } else {
            #pragma unroll
            for (int nt = 0; nt < 8; nt++) {
                float kf0 = kofft[8 * nt + 2 * tg], kf1 = kofft[8 * nt + 2 * tg + 1];
                float v0 = s[nt][0] + kf0;
                float v1 = s[nt][1] + kf1;
                float v2 = s[nt][2] + kf0;
                float v3 = s[nt][3] + kf1;
                s[nt][0] = v0; s[nt][1] = v1; s[nt][2] = v2; s[nt][3] = v3;
                mx0 = fmaxf(mx0, fmaxf(v0, v1));
                mx1 = fmaxf(mx1, fmaxf(v2, v3));
            }
        }
        mx0 = fmaxf(mx0, __shfl_xor_sync(0xffffffffu, mx0, 1));
        mx0 = fmaxf(mx0, __shfl_xor_sync(0xffffffffu, mx0, 2));
        mx1 = fmaxf(mx1, __shfl_xor_sync(0xffffffffu, mx1, 1));
        mx1 = fmaxf(mx1, __shfl_xor_sync(0xffffffffu, mx1, 2));

        float mn0 = fmaxf(m0v, mx0), mn1 = fmaxf(m1v, mx1);
        float al0 = ex2f(m0v - mn0), al1 = ex2f(m1v - mn1);
        m0v = mn0; m1v = mn1;
        l0 *= al0; l1 *= al1;

        #pragma unroll
        for (int nt = 0; nt < 8; nt++) {
            float p0 = ex2f(s[nt][0] - m0v);
            float p1 = ex2f(s[nt][1] - m0v);
            float p2 = ex2f(s[nt][2] - m1v);
            float p3 = ex2f(s[nt][3] - m1v);
            s[nt][0] = p0; s[nt][1] = p1; s[nt][2] = p2; s[nt][3] = p3;
            l0 += p0 + p1; l1 += p2 + p3;
        }
        #pragma unroll
        for (int nt = 0; nt < 8; nt++) {
            o[nt][0] *= al0; o[nt][1] *= al0;
            o[nt][2] *= al1; o[nt][3] *= al1;
        }

        // ---- O += P V ----
        #pragma unroll
        for (int ktP = 0; ktP < 4; ktP++) {
            int ntA = 2 * ktP, ntB = ntA + 1;
            uint32_t a0 = pk16(s[ntA][0], s[ntA][1]);
            uint32_t a1 = pk16(s[ntA][2], s[ntA][3]);
            uint32_t a2 = pk16(s[ntB][0], s[ntB][1]);
            uint32_t a3 = pk16(s[ntB][2], s[ntB][3]);
            #pragma unroll
            for (int p = 0; p < 4; p++) {
                uint32_t v0, v1, v2, v3;
                ldm4t(stV + (vboff[p] + 16 * ktP * AT_STRIDE) * 2, v0, v1, v2, v3);
                int n2A = 2 * p, n2B = n2A + 1;
                hmma16(o[n2A], a0, a1, a2, a3, v0, v1);
                hmma16(o[n2B], a0, a1, a2, a3, v2, v3);
            }
        }

        __syncthreads();
        if (kt_g + 2 <= ktmax) issueKV(kt_g + 2);
    }

    l0 += __shfl_xor_sync(0xffffffffu, l0, 1);
    l0 += __shfl_xor_sync(0xffffffffu, l0, 2);
    l1 += __shfl_xor_sync(0xffffffffu, l1, 1);
    l1 += __shfl_xor_sync(0xffffffffu, l1, 2);
    float inv0 = 1.f / l0, inv1 = 1.f / l1;

    #pragma unroll
    for (int nt = 0; nt < 8; nt++) {
        int col = hoff + 8 * nt + 2 * tg;
        *reinterpret_cast<uint32_t*>(ctx16 + (rowbase + r0g) * DD + col) =
            pk16(o[nt][0] * inv0, o[nt][1] * inv0);
        *reinterpret_cast<uint32_t*>(ctx16 + (rowbase + r1g) * DD + col) =
            pk16(o[nt][2] * inv1, o[nt][3] * inv1);
    }
}

// ---------------- host ---------------------------------------------------------
extern "C" void kernel_launch(void* const* d_in, const int* in_sizes, int n_in,
                              void* d_out, int out_size)
{
    const float* hidden = (const float*)d_in[0];
    const int*   amask  = (const int*)  d_in[1];
    const float* Wq     = (const float*)d_in[2];
    const float* Wk     = (const float*)d_in[3];
    const float* Wv     = (const float*)d_in[4];
    const float* Wo     = (const float*)d_in[5];
    const float* ln1g   = (const float*)d_in[6];
    const float* ln1b   = (const float*)d_in[7];
    const float* W1     = (const float*)d_in[8];
    const float* b1     = (const float*)d_in[9];
    const float* W2     = (const float*)d_in[10];
    const float* b2     = (const float*)d_in[11];
    const float* ln2g   = (const float*)d_in[12];
    const float* ln2b   = (const float*)d_in[13];
    float* out = (float*)d_out;

    __half *x16, *qkv16, *ctx16, *y16, *h16, *w16;
    float* x2;
    cudaGetSymbolAddress((void**)&x16,   g_x16);
    cudaGetSymbolAddress((void**)&qkv16, g_qkv16);
    cudaGetSymbolAddress((void**)&ctx16, g_ctx16);
    cudaGetSymbolAddress((void**)&x2,    g_x2);
    cudaGetSymbolAddress((void**)&y16,   g_y16);
    cudaGetSymbolAddress((void**)&h16,   g_h16);
    cudaGetSymbolAddress((void**)&w16,   g_w16);

    cudaFuncSetAttribute(attn_tc, cudaFuncAttributeMaxDynamicSharedMemorySize,
                         AT_SMEM_BYTES);
    cudaFuncSetAttribute(gemm_f16, cudaFuncAttributeMaxDynamicSharedMemorySize,
                         F16_SMEM);

    const int M = MROWS;

    trans16<<<dim3(DD/32, DD/32), 256>>>(Wq, w16,                  DD, DD);
    trans16<<<dim3(DD/32, DD/32), 256>>>(Wk, w16 + M1,             DD, DD);
    trans16<<<dim3(DD/32, DD/32), 256>>>(Wv, w16 + 2*(size_t)M1,   DD, DD);
    trans16<<<dim3(DD/32, DD/32), 256>>>(Wo, w16 + 3*(size_t)M1,   DD, DD);
    trans16<<<dim3(FF/32, DD/32), 256>>>(W1, w16 + 4*(size_t)M1,   DD, FF);
    trans16<<<dim3(DD/32, FF/32), 256>>>(W2, w16 + 8*(size_t)M1,   FF, DD);

    // LN1 -> fp16
    ln_f16<<<M, 256>>>(hidden, ln1g, ln1b, x16);
    // fused QKV projection -> fp16 (Q columns pre-scaled by 0.125*log2e)
    gemm_f16<<<dim3(QKVD/128, M/256), 512, F16_SMEM>>>(
        x16, w16, nullptr, nullptr, nullptr, qkv16, M, QKVD, DD, 0, DD);
    // attention -> ctx fp16
    attn_tc<<<dim3(SS/128, BB*HH), 256, AT_SMEM_BYTES>>>(qkv16, amask, ctx16);
    // output projection + residual -> fp32 x2
    gemm_f16<<<dim3(DD/128, M/256), 512, F16_SMEM>>>(
        ctx16, w16 + 3*(size_t)M1, nullptr, hidden, x2, nullptr, M, DD, DD, 0, 0);
    // LN2 -> fp16
    ln_f16<<<M, 256>>>(x2, ln2g, ln2b, y16);
    // FFN1 (bias + SiLU) -> fp16 h
    gemm_f16<<<dim3(FF/128, M/256), 512, F16_SMEM>>>(
        y16, w16 + 4*(size_t)M1, b1, nullptr, nullptr, h16, M, FF, DD, 1, 0);
    // FFN2 (bias + residual x2) -> fp32 out
    gemm_f16<<<dim3(DD/128, M/256), 512, F16_SMEM>>>(
        h16, w16 + 8*(size_t)M1, b2, x2, out, nullptr, M, DD, FF, 0, 0);
}

// round 12
// speedup vs baseline: 6.0662x; 1.1856x over previous
#include <cuda_runtime.h>
#include <cuda_fp16.h>
#include <math.h>
#include <stdint.h>

#define BB 4
#define SS 2048
#define DD 1024
#define FF 4096
#define HH 16
#define QKVD (3*DD)
#define NEGBIG -1e30f
#define MROWS (BB*SS)
#define M1 (DD*DD)
// 0.125 * log2(e) folded into Q
#define QSCALE 0.1803368801111204f

// ---------------- scratch ------------------------------------------------------
__device__ __half g_x16 [MROWS*DD];
__device__ __half g_qkv16[(size_t)MROWS*QKVD];
__device__ __half g_ctx16[MROWS*DD];
__device__ float  g_x2  [MROWS*DD];
__device__ __half g_y16 [MROWS*DD];
__device__ __half g_h16 [(size_t)MROWS*FF];
__device__ __half g_w16[(size_t)12*M1];

// ---------------- helpers ------------------------------------------------------
__device__ __forceinline__ uint32_t pk16(float a, float b) {
    __half2 h = __floats2half2_rn(a, b);
    return *reinterpret_cast<uint32_t*>(&h);
}
__device__ __forceinline__ float ex2f(float x) {
    float r;
    asm("ex2.approx.f32 %0, %1;" : "=f"(r) : "f"(x));
    return r;
}
__device__ __forceinline__ void hmma16(float* d, uint32_t a0, uint32_t a1,
                                       uint32_t a2, uint32_t a3,
                                       uint32_t b0, uint32_t b1) {
    asm volatile("mma.sync.aligned.m16n8k16.row.col.f32.f16.f16.f32 "
                 "{%0,%1,%2,%3}, {%4,%5,%6,%7}, {%8,%9}, {%0,%1,%2,%3};"
                 : "+f"(d[0]), "+f"(d[1]), "+f"(d[2]), "+f"(d[3])
                 : "r"(a0), "r"(a1), "r"(a2), "r"(a3), "r"(b0), "r"(b1));
}
__device__ __forceinline__ uint32_t s2u(const void* p) {
    return (uint32_t)__cvta_generic_to_shared(p);
}
__device__ __forceinline__ void cp16(uint32_t dst, const void* src) {
    asm volatile("cp.async.ca.shared.global [%0], [%1], 16;" :: "r"(dst), "l"(src));
}
__device__ __forceinline__ void cp_commit() { asm volatile("cp.async.commit_group;"); }
__device__ __forceinline__ void cp_wait0()  { asm volatile("cp.async.wait_group 0;"); }
__device__ __forceinline__ void cp_wait1()  { asm volatile("cp.async.wait_group 1;"); }
__device__ __forceinline__ void ldm4(uint32_t addr, uint32_t& r0, uint32_t& r1,
                                     uint32_t& r2, uint32_t& r3) {
    asm volatile("ldmatrix.sync.aligned.m8n8.x4.shared.b16 {%0,%1,%2,%3}, [%4];"
                 : "=r"(r0), "=r"(r1), "=r"(r2), "=r"(r3) : "r"(addr));
}
__device__ __forceinline__ void ldm4t(uint32_t addr, uint32_t& r0, uint32_t& r1,
                                      uint32_t& r2, uint32_t& r3) {
    asm volatile("ldmatrix.sync.aligned.m8n8.x4.trans.shared.b16 {%0,%1,%2,%3}, [%4];"
                 : "=r"(r0), "=r"(r1), "=r"(r2), "=r"(r3) : "r"(addr));
}

// ---------------- LayerNorm -> single fp16 -------------------------------------
__global__ __launch_bounds__(256)
void ln_f16(const float* __restrict__ x, const float* __restrict__ g,
            const float* __restrict__ b, __half* __restrict__ out16)
{
    int row = blockIdx.x;
    int tid = threadIdx.x;
    const float* xr = x + (size_t)row * DD;
    float4 v = *reinterpret_cast<const float4*>(xr + tid * 4);
    float s  = v.x + v.y + v.z + v.w;
    float sq = v.x*v.x + v.y*v.y + v.z*v.z + v.w*v.w;
    #pragma unroll
    for (int o = 16; o > 0; o >>= 1) {
        s  += __shfl_xor_sync(0xffffffffu, s,  o);
        sq += __shfl_xor_sync(0xffffffffu, sq, o);
    }
    __shared__ float ws[8], wq[8];
    __shared__ float smean, srstd;
    int wid = tid >> 5, lane = tid & 31;
    if (lane == 0) { ws[wid] = s; wq[wid] = sq; }
    __syncthreads();
    if (tid == 0) {
        float S = 0.f, Q = 0.f;
        #pragma unroll
        for (int i = 0; i < 8; i++) { S += ws[i]; Q += wq[i]; }
        float mean = S * (1.f / DD);
        float var  = fmaxf(Q * (1.f / DD) - mean * mean, 0.f);
        smean = mean;
        srstd = rsqrtf(var + 1e-12f);
    }
    __syncthreads();
    float mean = smean, rstd = srstd;
    float4 gv = *reinterpret_cast<const float4*>(g + tid * 4);
    float4 bv = *reinterpret_cast<const float4*>(b + tid * 4);
    uint2 pk = make_uint2(
        pk16((v.x - mean) * rstd * gv.x + bv.x, (v.y - mean) * rstd * gv.y + bv.y),
        pk16((v.z - mean) * rstd * gv.z + bv.z, (v.w - mean) * rstd * gv.w + bv.w));
    *reinterpret_cast<uint2*>(out16 + (size_t)row * DD + tid * 4) = pk;
}

// ---------------- weight transpose -> fp16 -------------------------------------
__global__ __launch_bounds__(256)
void trans16(const float* __restrict__ W, __half* __restrict__ hT, int K, int N)
{
    __shared__ float tile[32][33];
    int n0 = blockIdx.x * 32, k0 = blockIdx.y * 32;
    int tx = threadIdx.x & 31, ty = threadIdx.x >> 5;
    for (int j = ty; j < 32; j += 8)
        tile[j][tx] = W[(size_t)(k0 + j) * N + n0 + tx];
    __syncthreads();
    for (int j = ty; j < 32; j += 8)
        hT[(size_t)(n0 + j) * K + k0 + tx] = __float2half_rn(tile[tx][j]);
}

// ---------------- single-pass fp16 GEMM: 256x128 tile, BK=64, 2-stage -----------
#define GSTR 72
#define A_PLANE (256*GSTR)
#define B_PLANE (128*GSTR)
#define F16_STG (A_PLANE + B_PLANE)
#define F16_SMEM (2*F16_STG*2)

__global__ __launch_bounds__(512, 1)
void gemm_f16(const __half* __restrict__ A, const __half* __restrict__ B,
              const float* __restrict__ bias, const float* __restrict__ res,
              float* __restrict__ outF, __half* __restrict__ out16,
              int M, int N, int K, int act, int qcols)
{
    extern __shared__ uint16_t sh[];
    uint32_t sb = s2u(sh);
    int tid = threadIdx.x;
    int wid = tid >> 5, lane = tid & 31;
    int g = lane >> 2, tg = lane & 3;
    int q8 = lane >> 3, e8 = lane & 7;
    int warp_m = wid & 3, warp_n = wid >> 2;
    int m0 = blockIdx.y * 256, n0 = blockIdx.x * 128;
    float cscale = (n0 < qcols) ? QSCALE : 1.f;

    float acc[4][4][4];
    #pragma unroll
    for (int mt = 0; mt < 4; mt++)
        #pragma unroll
        for (int nt = 0; nt < 4; nt++)
            #pragma unroll
            for (int c = 0; c < 4; c++) acc[mt][nt][c] = 0.f;

    // cp.async: A 2048 + B 1024 chunks of 16B per stage -> 6/thread
    const __half* gp[6];
    uint32_t so[6];
    #pragma unroll
    for (int u = 0; u < 6; u++) {
        int f = tid + u * 512;
        if (f < 2048) {
            int row = f >> 3, c = (f & 7) << 3;
            gp[u] = A + (size_t)(m0 + row) * K + c;
            so[u] = (uint32_t)(row * GSTR + c) * 2;
        } else {
            int fb = f - 2048;
            int row = fb >> 3, c = (fb & 7) << 3;
            gp[u] = B + (size_t)(n0 + row) * K + c;
            so[u] = (uint32_t)(A_PLANE + row * GSTR + c) * 2;
        }
    }
    const int T = K >> 6;

    auto issue = [&](int t) {
        uint32_t st = sb + (uint32_t)(t & 1) * (F16_STG * 2);
        int k0 = t << 6;
        #pragma unroll
        for (int u = 0; u < 6; u++) cp16(st + so[u], gp[u] + k0);
        cp_commit();
    };

    issue(0);

    uint32_t aoff[4], boff[2];
    #pragma unroll
    for (int mt = 0; mt < 4; mt++)
        aoff[mt] = (uint32_t)((warp_m * 64 + mt * 16 + e8 + (q8 & 1) * 8) * GSTR
                              + (q8 >> 1) * 8);
    #pragma unroll
    for (int p = 0; p < 2; p++)
        boff[p] = (uint32_t)((warp_n * 32 + (2 * p + (q8 >> 1)) * 8 + e8) * GSTR
                             + (q8 & 1) * 8);

    for (int t = 0; t < T; t++) {
        cp_wait0();
        __syncthreads();
        if (t + 1 < T) issue(t + 1);

        uint32_t st = sb + (uint32_t)(t & 1) * (F16_STG * 2);
        #pragma unroll
        for (int ks = 0; ks < 64; ks += 16) {
            uint32_t af[4][4];
            #pragma unroll
            for (int mt = 0; mt < 4; mt++)
                ldm4(st + (aoff[mt] + ks) * 2,
                     af[mt][0], af[mt][1], af[mt][2], af[mt][3]);
            #pragma unroll
            for (int p = 0; p < 2; p++) {
                uint32_t b0, b1, b2, b3;
                ldm4(st + (A_PLANE + boff[p] + ks) * 2, b0, b1, b2, b3);
                int ntA = 2 * p, ntB = ntA + 1;
                #pragma unroll
                for (int mt = 0; mt < 4; mt++) {
                    hmma16(acc[mt][ntA], af[mt][0], af[mt][1], af[mt][2], af[mt][3], b0, b1);
                    hmma16(acc[mt][ntB], af[mt][0], af[mt][1], af[mt][2], af[mt][3], b2, b3);
                }
            }
        }
    }

    #pragma unroll
    for (int mt = 0; mt < 4; mt++) {
        #pragma unroll
        for (int nt = 0; nt < 4; nt++) {
            int row = m0 + warp_m * 64 + mt * 16 + g;
            int col = n0 + warp_n * 32 + nt * 8 + 2 * tg;
            #pragma unroll
            for (int half = 0; half < 2; half++) {
                int r = row + half * 8;
                float v0 = acc[mt][nt][half * 2 + 0];
                float v1 = acc[mt][nt][half * 2 + 1];
                if (bias) { v0 += bias[col]; v1 += bias[col + 1]; }
                if (act) {
                    v0 = v0 / (1.f + __expf(-v0));
                    v1 = v1 / (1.f + __expf(-v1));
                }
                v0 *= cscale; v1 *= cscale;
                size_t o = (size_t)r * N + col;
                if (outF) {
                    if (res) {
                        float2 rv = *reinterpret_cast<const float2*>(res + o);
                        v0 += rv.x; v1 += rv.y;
                    }
                    *reinterpret_cast<float2*>(outF + o) = make_float2(v0, v1);
                } else {
                    *reinterpret_cast<uint32_t*>(out16 + o) = pk16(v0, v1);
                }
            }
        }
    }
}

// ---------------- fp16 flash attention: 128 q-rows, 256 threads, 2 CTA/SM -------
#define AT_STRIDE 72
#define QPB (128*AT_STRIDE*2)
#define KPB (64*AT_STRIDE*2)
#define KV_BASE QPB
#define AT_SMEM_BYTES (KV_BASE + 4*KPB + 3*64*4)

__global__ __launch_bounds__(256, 2)
void attn_tc(const __half* __restrict__ qkv, const int* __restrict__ amask,
             __half* __restrict__ ctx16)
{
    extern __shared__ uint16_t ash[];
    uint32_t sb = s2u(ash);
    float* koff = reinterpret_cast<float*>((char*)ash + KV_BASE + 4 * KPB);

    int tid = threadIdx.x;
    int lane = tid & 31, w = tid >> 5;
    int g = lane >> 2, tg = lane & 3;
    int q8 = lane >> 3, e8 = lane & 7;
    int bh = blockIdx.y;
    int b = bh >> 4, h = bh & 15;
    int qt = gridDim.x - 1 - blockIdx.x;
    int q0 = qt * 128;
    const size_t rowbase = (size_t)b * SS;
    const int hoff = h * 64;
    const int ktmax = 2 * qt + 1;

    const __half* qgp[4]; uint32_t qso[4];
    #pragma unroll
    for (int u = 0; u < 4; u++) {
        int f = tid + u * 256;
        int row = f >> 3, c = (f & 7) << 3;
        qgp[u] = qkv + (rowbase + q0 + row) * QKVD + hoff + c;
        qso[u] = (uint32_t)(row * AT_STRIDE + c) * 2;
    }
    const __half* kvgp[4]; uint32_t kvso[4]; int kvrow[4];
    #pragma unroll
    for (int u = 0; u < 4; u++) {
        int f = tid + u * 256;
        int plane = f >> 9, fr = f & 511;
        int row = fr >> 3, c = (fr & 7) << 3;
        kvgp[u] = qkv + (plane ? 2 * DD : DD) + rowbase * QKVD + hoff + c;
        kvrow[u] = row;
        kvso[u] = (uint32_t)KV_BASE + (uint32_t)(plane * (KPB / 2) + row * AT_STRIDE + c) * 2;
    }

    auto issueKV = [&](int kt) {
        uint32_t st = sb + (uint32_t)(kt & 1) * (2 * KPB);
        int k0 = kt * 64;
        #pragma unroll
        for (int u = 0; u < 4; u++)
            cp16(st + kvso[u], kvgp[u] + (size_t)(k0 + kvrow[u]) * QKVD);
        cp_commit();
        if (tid < 64)
            koff[(kt % 3) * 64 + tid] = (amask[b * SS + k0 + tid] == 1) ? 0.f : NEGBIG;
    };

    #pragma unroll
    for (int u = 0; u < 4; u++) cp16(sb + qso[u], qgp[u]);
    cp_commit();
    issueKV(0);
    issueKV(1);
    cp_wait1();
    __syncthreads();

    uint32_t qf[4][4];
    uint32_t qoffb = (uint32_t)((w * 16 + e8 + (q8 & 1) * 8) * AT_STRIDE + (q8 >> 1) * 8);
    #pragma unroll
    for (int kt = 0; kt < 4; kt++)
        ldm4(sb + (qoffb + 16 * kt) * 2, qf[kt][0], qf[kt][1], qf[kt][2], qf[kt][3]);

    uint32_t kboff[4], vboff[4];
    #pragma unroll
    for (int p = 0; p < 4; p++) {
        kboff[p] = (uint32_t)(((2 * p + (q8 >> 1)) * 8 + e8) * AT_STRIDE + (q8 & 1) * 8);
        vboff[p] = (uint32_t)(((q8 & 1) * 8 + e8) * AT_STRIDE + (2 * p + (q8 >> 1)) * 8);
    }

    float o[8][4];
    #pragma unroll
    for (int nt = 0; nt < 8; nt++)
        #pragma unroll
        for (int c = 0; c < 4; c++) o[nt][c] = 0.f;
    float m0v = NEGBIG, m1v = NEGBIG, l0 = 0.f, l1 = 0.f;
    int r0g = q0 + w * 16 + g, r1g = r0g + 8;

    for (int kt_g = 0; kt_g <= ktmax; kt_g++) {
        int k0 = kt_g * 64;
        if (kt_g == ktmax) cp_wait0(); else cp_wait1();
        __syncthreads();

        uint32_t stK = sb + KV_BASE + (uint32_t)(kt_g & 1) * (2 * KPB);
        uint32_t stV = stK + KPB;
        const float* kofft = koff + (kt_g % 3) * 64;

        float s[8][4];
        #pragma unroll
        for (int nt = 0; nt < 8; nt++)
            #pragma unroll
            for (int c = 0; c < 4; c++) s[nt][c] = 0.f;
        #pragma unroll
        for (int kt = 0; kt < 4; kt++) {
            #pragma unroll
            for (int p = 0; p < 4; p++) {
                uint32_t b0, b1, b2, b3;
                ldm4(stK + (kboff[p] + 16 * kt) * 2, b0, b1, b2, b3);
                int ntA = 2 * p, ntB = ntA + 1;
                hmma16(s[ntA], qf[kt][0], qf[kt][1], qf[kt][2], qf[kt][3], b0, b1);
                hmma16(s[ntB], qf[kt][0], qf[kt][1], qf[kt][2], qf[kt][3], b2, b3);
            }
        }

        float mx0 = NEGBIG, mx1 = NEGBIG;
        if (kt_g >= 2 * qt) {
            #pragma unroll
            for (int nt = 0; nt < 8; nt++) {
                int c0 = k0 + 8 * nt + 2 * tg;
                float kf0 = kofft[8 * nt + 2 * tg], kf1 = kofft[8 * nt + 2 * tg + 1];
                float v0 = s[nt][0] + kf0;
                float v1 = s[nt][1] + kf1;
                float v2 = s[nt][2] + kf0;
                float v3 = s[nt][3] + kf1;
                if (c0     > r0g) v0 = NEGBIG;
                if (c0 + 1 > r0g) v1 = NEGBIG;
                if (c0     > r1g) v2 = NEGBIG;
                if (c0 + 1 > r1g) v3 = NEGBIG;
                s[nt][0] = v0; s[nt][1] = v1; s[nt][2] = v2; s[nt][3] = v3;
                mx0 = fmaxf(mx0, fmaxf(v0, v1));
                mx1 = fmaxf(mx1, fmaxf(v2, v3));
            }
        } else {
            #pragma unroll
            for (int nt = 0; nt < 8; nt++) {
                float kf0 = kofft[8 * nt + 2 * tg], kf1 = kofft[8 * nt + 2 * tg + 1];
                float v0 = s[nt][0] + kf0;
                float v1 = s[nt][1] + kf1;
                float v2 = s[nt][2] + kf0;
                float v3 = s[nt][3] + kf1;
                s[nt][0] = v0; s[nt][1] = v1; s[nt][2] = v2; s[nt][3] = v3;
                mx0 = fmaxf(mx0, fmaxf(v0, v1));
                mx1 = fmaxf(mx1, fmaxf(v2, v3));
            }
        }
        mx0 = fmaxf(mx0, __shfl_xor_sync(0xffffffffu, mx0, 1));
        mx0 = fmaxf(mx0, __shfl_xor_sync(0xffffffffu, mx0, 2));
        mx1 = fmaxf(mx1, __shfl_xor_sync(0xffffffffu, mx1, 1));
        mx1 = fmaxf(mx1, __shfl_xor_sync(0xffffffffu, mx1, 2));

        float mn0 = fmaxf(m0v, mx0), mn1 = fmaxf(m1v, mx1);
        float al0 = ex2f(m0v - mn0), al1 = ex2f(m1v - mn1);
        m0v = mn0; m1v = mn1;
        l0 *= al0; l1 *= al1;

        #pragma unroll
        for (int nt = 0; nt < 8; nt++) {
            float p0 = ex2f(s[nt][0] - m0v);
            float p1 = ex2f(s[nt][1] - m0v);
            float p2 = ex2f(s[nt][2] - m1v);
            float p3 = ex2f(s[nt][3] - m1v);
            s[nt][0] = p0; s[nt][1] = p1; s[nt][2] = p2; s[nt][3] = p3;
            l0 += p0 + p1; l1 += p2 + p3;
        }
        #pragma unroll
        for (int nt = 0; nt < 8; nt++) {
            o[nt][0] *= al0; o[nt][1] *= al0;
            o[nt][2] *= al1; o[nt][3] *= al1;
        }

        #pragma unroll
        for (int ktP = 0; ktP < 4; ktP++) {
            int ntA = 2 * ktP, ntB = ntA + 1;
            uint32_t a0 = pk16(s[ntA][0], s[ntA][1]);
            uint32_t a1 = pk16(s[ntA][2], s[ntA][3]);
            uint32_t a2 = pk16(s[ntB][0], s[ntB][1]);
            uint32_t a3 = pk16(s[ntB][2], s[ntB][3]);
            #pragma unroll
            for (int p = 0; p < 4; p++) {
                uint32_t v0, v1, v2, v3;
                ldm4t(stV + (vboff[p] + 16 * ktP * AT_STRIDE) * 2, v0, v1, v2, v3);
                int n2A = 2 * p, n2B = n2A + 1;
                hmma16(o[n2A], a0, a1, a2, a3, v0, v1);
                hmma16(o[n2B], a0, a1, a2, a3, v2, v3);
            }
        }

        __syncthreads();
        if (kt_g + 2 <= ktmax) issueKV(kt_g + 2);
    }

    l0 += __shfl_xor_sync(0xffffffffu, l0, 1);
    l0 += __shfl_xor_sync(0xffffffffu, l0, 2);
    l1 += __shfl_xor_sync(0xffffffffu, l1, 1);
    l1 += __shfl_xor_sync(0xffffffffu, l1, 2);
    float inv0 = 1.f / l0, inv1 = 1.f / l1;

    #pragma unroll
    for (int nt = 0; nt < 8; nt++) {
        int col = hoff + 8 * nt + 2 * tg;
        *reinterpret_cast<uint32_t*>(ctx16 + (rowbase + r0g) * DD + col) =
            pk16(o[nt][0] * inv0, o[nt][1] * inv0);
        *reinterpret_cast<uint32_t*>(ctx16 + (rowbase + r1g) * DD + col) =
            pk16(o[nt][2] * inv1, o[nt][3] * inv1);
    }
}

// ---------------- host ---------------------------------------------------------
extern "C" void kernel_launch(void* const* d_in, const int* in_sizes, int n_in,
                              void* d_out, int out_size)
{
    const float* hidden = (const float*)d_in[0];
    const int*   amask  = (const int*)  d_in[1];
    const float* Wq     = (const float*)d_in[2];
    const float* Wk     = (const float*)d_in[3];
    const float* Wv     = (const float*)d_in[4];
    const float* Wo     = (const float*)d_in[5];
    const float* ln1g   = (const float*)d_in[6];
    const float* ln1b   = (const float*)d_in[7];
    const float* W1     = (const float*)d_in[8];
    const float* b1     = (const float*)d_in[9];
    const float* W2     = (const float*)d_in[10];
    const float* b2     = (const float*)d_in[11];
    const float* ln2g   = (const float*)d_in[12];
    const float* ln2b   = (const float*)d_in[13];
    float* out = (float*)d_out;

    __half *x16, *qkv16, *ctx16, *y16, *h16, *w16;
    float* x2;
    cudaGetSymbolAddress((void**)&x16,   g_x16);
    cudaGetSymbolAddress((void**)&qkv16, g_qkv16);
    cudaGetSymbolAddress((void**)&ctx16, g_ctx16);
    cudaGetSymbolAddress((void**)&x2,    g_x2);
    cudaGetSymbolAddress((void**)&y16,   g_y16);
    cudaGetSymbolAddress((void**)&h16,   g_h16);
    cudaGetSymbolAddress((void**)&w16,   g_w16);

    cudaFuncSetAttribute(attn_tc, cudaFuncAttributeMaxDynamicSharedMemorySize,
                         AT_SMEM_BYTES);
    cudaFuncSetAttribute(gemm_f16, cudaFuncAttributeMaxDynamicSharedMemorySize,
                         F16_SMEM);

    const int M = MROWS;

    trans16<<<dim3(DD/32, DD/32), 256>>>(Wq, w16,                  DD, DD);
    trans16<<<dim3(DD/32, DD/32), 256>>>(Wk, w16 + M1,             DD, DD);
    trans16<<<dim3(DD/32, DD/32), 256>>>(Wv, w16 + 2*(size_t)M1,   DD, DD);
    trans16<<<dim3(DD/32, DD/32), 256>>>(Wo, w16 + 3*(size_t)M1,   DD, DD);
    trans16<<<dim3(FF/32, DD/32), 256>>>(W1, w16 + 4*(size_t)M1,   DD, FF);
    trans16<<<dim3(DD/32, FF/32), 256>>>(W2, w16 + 8*(size_t)M1,   FF, DD);

    // LN1 -> fp16
    ln_f16<<<M, 256>>>(hidden, ln1g, ln1b, x16);
    // fused QKV projection -> fp16 (Q columns pre-scaled by 0.125*log2e)
    gemm_f16<<<dim3(QKVD/128, M/256), 512, F16_SMEM>>>(
        x16, w16, nullptr, nullptr, nullptr, qkv16, M, QKVD, DD, 0, DD);
    // attention -> ctx fp16
    attn_tc<<<dim3(SS/128, BB*HH), 256, AT_SMEM_BYTES>>>(qkv16, amask, ctx16);
    // output projection + residual -> fp32 x2
    gemm_f16<<<dim3(DD/128, M/256), 512, F16_SMEM>>>(
        ctx16, w16 + 3*(size_t)M1, nullptr, hidden, x2, nullptr, M, DD, DD, 0, 0);
    // LN2 -> fp16
    ln_f16<<<M, 256>>>(x2, ln2g, ln2b, y16);
    // FFN1 (bias + SiLU) -> fp16 h
    gemm_f16<<<dim3(FF/128, M/256), 512, F16_SMEM>>>(
        y16, w16 + 4*(size_t)M1, b1, nullptr, nullptr, h16, M, FF, DD, 1, 0);
    // FFN2 (bias + residual x2) -> fp32 out
    gemm_f16<<<dim3(DD/128, M/256), 512, F16_SMEM>>>(
        h16, w16 + 8*(size_t)M1, b2, x2, out, nullptr, M, DD, FF, 0, 0);
}